// round 1
// baseline (speedup 1.0000x reference)
#include <cuda_runtime.h>
#include <math.h>

#define Bq 4
#define Hh 8
#define Tt 4096
#define Dd 64
#define NCc 16
#define WSZc 256

// ---------------- scratch (no allocations allowed) ----------------
__device__ float g_x[Bq * Hh * Tt * Dd];          // normalized k, 32MB
__device__ float g_dists[Bq * Hh * NCc * Tt];     // [bh, c, t], 8MB
__device__ int   g_idx[Bq * Hh * NCc * WSZc];     // sorted top-k indices
__device__ int   g_cnt[Bq * Hh * Tt];             // scatter counts
__device__ float g_aux;                           // commitment loss sum

// ---------------- kernel 0: zero out / cnt / aux ----------------
__global__ void zero_kernel(float* out, long long n_out) {
    long long i = (long long)blockIdx.x * blockDim.x + threadIdx.x;
    long long stride = (long long)gridDim.x * blockDim.x;
    for (long long p = i; p < n_out; p += stride) out[p] = 0.f;
    for (long long p = i; p < (long long)Bq * Hh * Tt; p += stride) g_cnt[p] = 0;
    if (i == 0) g_aux = 0.f;
}

// ---------------- kernel 1: normalize + dists + argmax + aux ----------------
// one warp per token; 8 tokens per 256-thread block (all same (b,h))
__global__ void route_kernel(const float* __restrict__ k,
                             const float* __restrict__ means) {
    __shared__ float sm[NCc * Dd];
    __shared__ float saux;
    int token0 = blockIdx.x * 8;
    int bh = token0 / Tt;
    int h = bh % Hh;
    const float* mh = means + (size_t)h * NCc * Dd;
    for (int i = threadIdx.x; i < NCc * Dd; i += blockDim.x) sm[i] = mh[i];
    if (threadIdx.x == 0) saux = 0.f;
    __syncthreads();

    int warp = threadIdx.x >> 5, lane = threadIdx.x & 31;
    int token = token0 + warp;
    int t = token & (Tt - 1);

    float2 kv = ((const float2*)(k + (size_t)token * Dd))[lane];
    float ss = kv.x * kv.x + kv.y * kv.y;
#pragma unroll
    for (int o = 16; o; o >>= 1) ss += __shfl_xor_sync(0xffffffffu, ss, o);
    float inv = rsqrtf(ss);  // norm ~ sqrt(64): never near 0 for random k
    float2 xv = make_float2(kv.x * inv, kv.y * inv);
    ((float2*)(g_x + (size_t)token * Dd))[lane] = xv;

    float dl[NCc];
#pragma unroll
    for (int c = 0; c < NCc; c++)
        dl[c] = xv.x * sm[c * Dd + 2 * lane] + xv.y * sm[c * Dd + 2 * lane + 1];
#pragma unroll
    for (int o = 16; o; o >>= 1) {
#pragma unroll
        for (int c = 0; c < NCc; c++)
            dl[c] += __shfl_xor_sync(0xffffffffu, dl[c], o);
    }
    // all lanes hold the full 16 sums now
    int bestc = 0;
    float bestv = dl[0];
#pragma unroll
    for (int c = 1; c < NCc; c++)
        if (dl[c] > bestv) { bestv = dl[c]; bestc = c; }  // first-max tie-break

    if (lane == 0) {
#pragma unroll
        for (int c = 0; c < NCc; c++)
            g_dists[((size_t)bh * NCc + c) * Tt + t] = dl[c];
    }

    // commitment loss partial: (x - means[h, bucket])^2
    float mx = sm[bestc * Dd + 2 * lane];
    float my = sm[bestc * Dd + 2 * lane + 1];
    float ex = xv.x - mx, ey = xv.y - my;
    float e = ex * ex + ey * ey;
#pragma unroll
    for (int o = 16; o; o >>= 1) e += __shfl_xor_sync(0xffffffffu, e, o);
    if (lane == 0) atomicAdd(&saux, e);
    __syncthreads();
    if (threadIdx.x == 0) atomicAdd(&g_aux, saux);
}

// ---------------- kernel 2: top-WSZ per (b,h,c) + sort indices ----------------
// key = (~orderable(value) << 32) | index  -> ascending sort == value desc, idx asc
__global__ void topk_kernel() {
    __shared__ unsigned long long key[Tt];   // 32KB
    __shared__ int sidx[WSZc];
    int bhc = blockIdx.x;
    const float* dc = g_dists + (size_t)bhc * Tt;

    for (int i = threadIdx.x; i < Tt; i += blockDim.x) {
        unsigned u = __float_as_uint(dc[i]);
        u = (u & 0x80000000u) ? ~u : (u | 0x80000000u);  // monotone float->uint
        key[i] = ((unsigned long long)(~u) << 32) | (unsigned)i;
    }
    __syncthreads();

    for (int kk = 2; kk <= Tt; kk <<= 1) {
        for (int j = kk >> 1; j > 0; j >>= 1) {
            for (int i = threadIdx.x; i < Tt; i += blockDim.x) {
                int ixj = i ^ j;
                if (ixj > i) {
                    unsigned long long a = key[i], b = key[ixj];
                    bool up = ((i & kk) == 0);
                    if ((a > b) == up) { key[i] = b; key[ixj] = a; }
                }
            }
            __syncthreads();
        }
    }

    // first WSZ keys = top WSZ values; extract indices, sort ascending
    sidx[threadIdx.x] = (int)(key[threadIdx.x] & 0xffffffffu);
    __syncthreads();
    for (int kk = 2; kk <= WSZc; kk <<= 1) {
        for (int j = kk >> 1; j > 0; j >>= 1) {
            int i = threadIdx.x;
            int ixj = i ^ j;
            if (ixj > i) {
                int a = sidx[i], b = sidx[ixj];
                bool up = ((i & kk) == 0);
                if ((a > b) == up) { sidx[i] = b; sidx[ixj] = a; }
            }
            __syncthreads();
        }
    }

    int bh = bhc / NCc;
    int id = sidx[threadIdx.x];
    g_idx[(size_t)bhc * WSZc + threadIdx.x] = id;
    atomicAdd(&g_cnt[bh * Tt + id], 1);
}

// ---------------- kernel 3: windowed causal attention + scatter-add ----------------
// one block per (b,h,c); thread i = query row i of the 256-wide window.
// scores = (q . x_hat)/8, |s| small -> exp without max-subtraction is safe.
__global__ void __launch_bounds__(256) attn_kernel(const float* __restrict__ q,
                                                   const float* __restrict__ v,
                                                   float* __restrict__ out) {
    __shared__ int sidx[WSZc];
    __shared__ float kch[64 * 64];  // 16KB chunk of gathered x
    __shared__ float vch[64 * 64];  // 16KB chunk of gathered v
    int bhc = blockIdx.x;
    int bh = bhc / NCc;
    int tid = threadIdx.x;

    sidx[tid] = g_idx[(size_t)bhc * WSZc + tid];
    __syncthreads();

    size_t qbase = ((size_t)bh * Tt + sidx[tid]) * Dd;
    float4 qv[16];
    const float4* qp = (const float4*)(q + qbase);
#pragma unroll
    for (int r = 0; r < 16; r++) qv[r] = qp[r];

    float4 acc[16];
#pragma unroll
    for (int r = 0; r < 16; r++) acc[r] = make_float4(0.f, 0.f, 0.f, 0.f);
    float l = 0.f;

    int row = tid >> 2, part = tid & 3;  // cooperative chunk loads
    for (int jc = 0; jc < 4; jc++) {
        __syncthreads();
        {
            int gj = sidx[jc * 64 + row];
            size_t rb = ((size_t)bh * Tt + gj) * Dd;
            const float4* ksrc = (const float4*)(g_x + rb) + part * 4;
            const float4* vsrc = (const float4*)(v + rb) + part * 4;
            float4* kdst = (float4*)(kch + row * 64) + part * 4;
            float4* vdst = (float4*)(vch + row * 64) + part * 4;
#pragma unroll
            for (int r = 0; r < 4; r++) { kdst[r] = ksrc[r]; vdst[r] = vsrc[r]; }
        }
        __syncthreads();

        int lim = tid - jc * 64;  // j <= i  <=>  jj <= lim
        if (lim >= 0) {
            int jjmax = lim < 63 ? lim : 63;
            for (int jj = 0; jj <= jjmax; jj++) {
                const float4* kr = (const float4*)(kch + jj * 64);
                float dot = 0.f;
#pragma unroll
                for (int r = 0; r < 16; r++) {
                    float4 kk4 = kr[r];
                    dot += qv[r].x * kk4.x + qv[r].y * kk4.y +
                           qv[r].z * kk4.z + qv[r].w * kk4.w;
                }
                float p;
                if (jj == lim) {
                    // diagonal: reference sets -50000 -> weight 0 unless this is
                    // the only unmasked entry (row 0), where softmax gives 1.
                    p = (tid == 0) ? 1.f : 0.f;
                } else {
                    p = __expf(dot * 0.125f);
                }
                l += p;
                const float4* vr = (const float4*)(vch + jj * 64);
#pragma unroll
                for (int r = 0; r < 16; r++) {
                    float4 vv = vr[r];
                    acc[r].x += p * vv.x; acc[r].y += p * vv.y;
                    acc[r].z += p * vv.z; acc[r].w += p * vv.w;
                }
            }
        }
    }

    float invl = 1.f / l;
    float* orow = out + qbase;
#pragma unroll
    for (int r = 0; r < 16; r++) {
        atomicAdd(orow + 4 * r + 0, acc[r].x * invl);
        atomicAdd(orow + 4 * r + 1, acc[r].y * invl);
        atomicAdd(orow + 4 * r + 2, acc[r].z * invl);
        atomicAdd(orow + 4 * r + 3, acc[r].w * invl);
    }
}

// ---------------- kernel 4: divide by count + aux loss ----------------
__global__ void finalize_kernel(float* out, int out_size) {
    const int n = Bq * Hh * Tt * Dd;
    int i = blockIdx.x * blockDim.x + threadIdx.x;
    int stride = gridDim.x * blockDim.x;
    for (int p = i; p < n; p += stride) {
        float cc = (float)g_cnt[p >> 6];
        out[p] = out[p] / (cc + 1e-5f);
    }
    if (i == 0 && out_size > n) {
        out[n] = g_aux * (1e-4f / (float)n);
    }
}

// ---------------- launch ----------------
extern "C" void kernel_launch(void* const* d_in, const int* in_sizes, int n_in,
                              void* d_out, int out_size) {
    const float* q = (const float*)d_in[0];
    const float* k = (const float*)d_in[1];
    const float* v = (const float*)d_in[2];
    const float* means = (const float*)d_in[3];
    float* out = (float*)d_out;

    zero_kernel<<<4096, 256>>>(out, (long long)out_size);
    route_kernel<<<Bq * Hh * Tt / 8, 256>>>(k, means);
    topk_kernel<<<Bq * Hh * NCc, 256>>>();
    attn_kernel<<<Bq * Hh * NCc, 256>>>(q, v, out);
    finalize_kernel<<<4096, 256>>>(out, out_size);
}

// round 2
// speedup vs baseline: 1.4862x; 1.4862x over previous
#include <cuda_runtime.h>
#include <math.h>

#define Bq 4
#define Hh 8
#define Tt 4096
#define Dd 64
#define NCc 16
#define WSZc 256

#define KSTR 68
#define PSTR 68
// dynamic smem floats: Q[64][256] + K[64][KSTR] + V[64][KSTR] + P[256][PSTR]
#define ATTN_SMEM_FLOATS (64*256 + 64*KSTR + 64*KSTR + 256*PSTR)
#define ATTN_SMEM_BYTES (ATTN_SMEM_FLOATS * 4)

// ---------------- scratch (no allocations allowed) ----------------
__device__ float g_x[Bq * Hh * Tt * Dd];          // normalized k, 32MB
__device__ float g_dists[Bq * Hh * NCc * Tt];     // [bh, c, t], 8MB
__device__ int   g_idx[Bq * Hh * NCc * WSZc];     // sorted top-k indices
__device__ int   g_cnt[Bq * Hh * Tt];             // scatter counts
__device__ float g_aux;                           // commitment loss sum

// ---------------- kernel 0: zero out / cnt / aux ----------------
__global__ void zero_kernel(float* out, long long n_out) {
    long long i = (long long)blockIdx.x * blockDim.x + threadIdx.x;
    long long stride = (long long)gridDim.x * blockDim.x;
    for (long long p = i; p < n_out; p += stride) out[p] = 0.f;
    for (long long p = i; p < (long long)Bq * Hh * Tt; p += stride) g_cnt[p] = 0;
    if (i == 0) g_aux = 0.f;
}

// ---------------- kernel 1: normalize + dists + argmax + aux ----------------
__global__ void route_kernel(const float* __restrict__ k,
                             const float* __restrict__ means) {
    __shared__ float sm[NCc * Dd];
    __shared__ float saux;
    int token0 = blockIdx.x * 8;
    int bh = token0 / Tt;
    int h = bh % Hh;
    const float* mh = means + (size_t)h * NCc * Dd;
    for (int i = threadIdx.x; i < NCc * Dd; i += blockDim.x) sm[i] = mh[i];
    if (threadIdx.x == 0) saux = 0.f;
    __syncthreads();

    int warp = threadIdx.x >> 5, lane = threadIdx.x & 31;
    int token = token0 + warp;
    int t = token & (Tt - 1);

    float2 kv = ((const float2*)(k + (size_t)token * Dd))[lane];
    float ss = kv.x * kv.x + kv.y * kv.y;
#pragma unroll
    for (int o = 16; o; o >>= 1) ss += __shfl_xor_sync(0xffffffffu, ss, o);
    float inv = rsqrtf(ss);
    float2 xv = make_float2(kv.x * inv, kv.y * inv);
    ((float2*)(g_x + (size_t)token * Dd))[lane] = xv;

    float dl[NCc];
#pragma unroll
    for (int c = 0; c < NCc; c++)
        dl[c] = xv.x * sm[c * Dd + 2 * lane] + xv.y * sm[c * Dd + 2 * lane + 1];
#pragma unroll
    for (int o = 16; o; o >>= 1) {
#pragma unroll
        for (int c = 0; c < NCc; c++)
            dl[c] += __shfl_xor_sync(0xffffffffu, dl[c], o);
    }
    int bestc = 0;
    float bestv = dl[0];
#pragma unroll
    for (int c = 1; c < NCc; c++)
        if (dl[c] > bestv) { bestv = dl[c]; bestc = c; }

    if (lane == 0) {
#pragma unroll
        for (int c = 0; c < NCc; c++)
            g_dists[((size_t)bh * NCc + c) * Tt + t] = dl[c];
    }

    float mx = sm[bestc * Dd + 2 * lane];
    float my = sm[bestc * Dd + 2 * lane + 1];
    float ex = xv.x - mx, ey = xv.y - my;
    float e = ex * ex + ey * ey;
#pragma unroll
    for (int o = 16; o; o >>= 1) e += __shfl_xor_sync(0xffffffffu, e, o);
    if (lane == 0) atomicAdd(&saux, e);
    __syncthreads();
    if (threadIdx.x == 0) atomicAdd(&g_aux, saux);
}

// ---------------- kernel 2: radix-select top-WSZ per (b,h,c) ----------------
// find bin holding rank-K element (from the top), update K to rank within bin.
__device__ __forceinline__ void find_bin(unsigned* h, unsigned* sscan,
                                         unsigned* s_bin, unsigned* s_k, int tid) {
    unsigned K = *s_k;
    unsigned tot = 0;
#pragma unroll
    for (int r = 0; r < 16; r++) tot += h[tid * 16 + r];
    sscan[tid] = tot;
    __syncthreads();
    for (int off = 1; off < 256; off <<= 1) {
        unsigned vv = (tid + off < 256) ? sscan[tid + off] : 0u;
        __syncthreads();
        sscan[tid] += vv;
        __syncthreads();
    }
    unsigned above = (tid < 255) ? sscan[tid + 1] : 0u;  // suffix over higher threads
    unsigned run = above;
#pragma unroll
    for (int r = 15; r >= 0; r--) {
        unsigned c = h[tid * 16 + r];
        run += c;  // = suffix(bin = tid*16+r)
        if (run >= K && run - c < K) {
            *s_bin = (unsigned)(tid * 16 + r);
            *s_k = K - (run - c);
        }
    }
    __syncthreads();
}

__global__ void __launch_bounds__(256) topk_kernel() {
    __shared__ unsigned su[Tt];      // monotone-mapped keys, 16KB
    __shared__ unsigned h[4096];     // histogram, 16KB
    __shared__ unsigned sscan[256];
    __shared__ unsigned s_bin, s_k;
    int tid = threadIdx.x;
    int bhc = blockIdx.x;
    const float* dc = g_dists + (size_t)bhc * Tt;

    for (int i = tid; i < Tt; i += 256) {
        unsigned uu = __float_as_uint(dc[i]);
        uu = (uu & 0x80000000u) ? ~uu : (uu | 0x80000000u);
        su[i] = uu;
        h[i] = 0u;
    }
    if (tid == 0) s_k = WSZc;
    __syncthreads();

    // pass 1: bits [31:20]
    for (int i = tid; i < Tt; i += 256) atomicAdd(&h[su[i] >> 20], 1u);
    __syncthreads();
    find_bin(h, sscan, &s_bin, &s_k, tid);
    unsigned b1 = s_bin;
    for (int i = tid; i < 4096; i += 256) h[i] = 0u;
    __syncthreads();

    // pass 2: bits [19:8] among candidates
    for (int i = tid; i < Tt; i += 256)
        if ((su[i] >> 20) == b1) atomicAdd(&h[(su[i] >> 8) & 0xFFFu], 1u);
    __syncthreads();
    find_bin(h, sscan, &s_bin, &s_k, tid);
    unsigned b2 = s_bin;
    for (int i = tid; i < 4096; i += 256) h[i] = 0u;
    __syncthreads();

    // pass 3: bits [7:0]
    unsigned hi20 = (b1 << 12) | b2;
    for (int i = tid; i < Tt; i += 256)
        if ((su[i] >> 8) == hi20) atomicAdd(&h[su[i] & 0xFFu], 1u);
    __syncthreads();
    find_bin(h, sscan, &s_bin, &s_k, tid);
    unsigned b3 = s_bin;
    unsigned m = s_k;                       // # of ties (==thr) to take, lowest index first
    unsigned thr = (b1 << 20) | (b2 << 8) | b3;

    // ordered compaction: thread owns contiguous [tid*16, tid*16+16)
    unsigned gt = 0, eq = 0;
    int base = tid * 16;
#pragma unroll
    for (int r = 0; r < 16; r++) {
        unsigned uu = su[base + r];
        gt += (uu > thr);
        eq += (uu == thr);
    }
    unsigned mypack = (gt << 16) | eq;
    sscan[tid] = mypack;
    __syncthreads();
    for (int off = 1; off < 256; off <<= 1) {
        unsigned vv = (tid >= off) ? sscan[tid - off] : 0u;
        __syncthreads();
        sscan[tid] += vv;
        __syncthreads();
    }
    unsigned excl = sscan[tid] - mypack;
    unsigned gtb = excl >> 16, eqb = excl & 0xFFFFu;
    int bh = bhc >> 4;
#pragma unroll
    for (int r = 0; r < 16; r++) {
        unsigned uu = su[base + r];
        if (uu > thr) {
            unsigned emin = eqb < m ? eqb : m;
            int pos = (int)(gtb + emin);
            g_idx[(size_t)bhc * WSZc + pos] = base + r;
            atomicAdd(&g_cnt[bh * Tt + base + r], 1);
            gtb++;
        } else if (uu == thr) {
            if (eqb < m) {
                int pos = (int)(gtb + eqb);
                g_idx[(size_t)bhc * WSZc + pos] = base + r;
                atomicAdd(&g_cnt[bh * Tt + base + r], 1);
            }
            eqb++;
        }
    }
}

// ---------------- kernel 3: register-tiled windowed attention ----------------
// block = one window (256 q x 256 k, D=64). 256 threads, 8x8 tile each.
// thread (ti = tid>>3, tj = tid&7): GEMM1 S rows ti*8.., cols tj*8.. of key chunk;
// GEMM2 O rows ti*8.., d-cols tj*8..
__global__ void __launch_bounds__(256, 1) attn_kernel(const float* __restrict__ q,
                                                      const float* __restrict__ v,
                                                      float* __restrict__ out) {
    extern __shared__ float smd[];
    float* sQ = smd;                       // [64 d][256 i]
    float* sK = sQ + 64 * 256;             // [64 d][KSTR j]
    float* sV = sK + 64 * KSTR;            // [64 j][KSTR d]
    float* sP = sV + 64 * KSTR;            // [256 i][PSTR], 16B lines XOR-swizzled
    __shared__ int sidx[WSZc];
    __shared__ float sl[WSZc];

    int tid = threadIdx.x;
    int bhc = blockIdx.x;
    int bh = bhc >> 4;
    int ti = tid >> 3, tj = tid & 7;
    int swz = ti & 3;

    sidx[tid] = g_idx[(size_t)bhc * WSZc + tid];
    sl[tid] = 0.f;
    __syncthreads();

    // load Q transposed: thread tid owns query row tid
    {
        int gi = sidx[tid];
        const float4* qs = (const float4*)(q + ((size_t)bh * Tt + gi) * Dd);
#pragma unroll
        for (int r = 0; r < 16; r++) {
            float4 a = qs[r];
            sQ[(r * 4 + 0) * 256 + tid] = a.x;
            sQ[(r * 4 + 1) * 256 + tid] = a.y;
            sQ[(r * 4 + 2) * 256 + tid] = a.z;
            sQ[(r * 4 + 3) * 256 + tid] = a.w;
        }
    }

    float o[8][8];
#pragma unroll
    for (int a = 0; a < 8; a++)
#pragma unroll
        for (int b = 0; b < 8; b++) o[a][b] = 0.f;
    float lp[8];
#pragma unroll
    for (int a = 0; a < 8; a++) lp[a] = 0.f;

    for (int jc = 0; jc < 4; jc++) {
        __syncthreads();
        // gather K chunk (transposed) + V chunk (row-major)
        {
            int r = tid >> 2, part = tid & 3;
            int gj = sidx[jc * 64 + r];
            const float4* xs = (const float4*)(g_x + ((size_t)bh * Tt + gj) * Dd) + part * 4;
            const float4* vs = (const float4*)(v + ((size_t)bh * Tt + gj) * Dd) + part * 4;
#pragma unroll
            for (int q4 = 0; q4 < 4; q4++) {
                float4 kk = xs[q4];
                int d0 = part * 16 + q4 * 4;
                sK[(d0 + 0) * KSTR + r] = kk.x;
                sK[(d0 + 1) * KSTR + r] = kk.y;
                sK[(d0 + 2) * KSTR + r] = kk.z;
                sK[(d0 + 3) * KSTR + r] = kk.w;
                *(float4*)&sV[r * KSTR + d0] = vs[q4];
            }
        }
        __syncthreads();

        // warp-uniform skip: chunk fully above the diagonal for these rows
        bool active = (jc * 64 <= ti * 8 + 7);
        if (active) {
            // ---- GEMM1: S = Q . K^T ----
            float s[8][8];
#pragma unroll
            for (int a = 0; a < 8; a++)
#pragma unroll
                for (int b = 0; b < 8; b++) s[a][b] = 0.f;
#pragma unroll 4
            for (int d = 0; d < 64; d++) {
                float4 a0 = *(const float4*)&sQ[d * 256 + ti * 8];
                float4 a1 = *(const float4*)&sQ[d * 256 + ti * 8 + 4];
                float4 b0 = *(const float4*)&sK[d * KSTR + tj * 8];
                float4 b1 = *(const float4*)&sK[d * KSTR + tj * 8 + 4];
                float aa[8] = {a0.x, a0.y, a0.z, a0.w, a1.x, a1.y, a1.z, a1.w};
                float bb[8] = {b0.x, b0.y, b0.z, b0.w, b1.x, b1.y, b1.z, b1.w};
#pragma unroll
                for (int a = 0; a < 8; a++)
#pragma unroll
                    for (int b = 0; b < 8; b++) s[a][b] += aa[a] * bb[b];
            }
            // ---- mask + exp + rowsum + store P (swizzled float4 lines) ----
#pragma unroll
            for (int a = 0; a < 8; a++) {
                int i = ti * 8 + a;
#pragma unroll
                for (int b = 0; b < 8; b++) {
                    int j = jc * 64 + tj * 8 + b;
                    float p;
                    if (j > i) p = 0.f;
                    else if (j == i) p = (i == 0) ? 1.f : 0.f;  // diag = -50000 in ref
                    else p = __expf(s[a][b] * 0.125f);
                    s[a][b] = p;
                    lp[a] += p;
                }
                int l0 = (tj * 2 + 0) ^ swz;
                int l1 = (tj * 2 + 1) ^ swz;
                *(float4*)&sP[i * PSTR + l0 * 4] = make_float4(s[a][0], s[a][1], s[a][2], s[a][3]);
                *(float4*)&sP[i * PSTR + l1 * 4] = make_float4(s[a][4], s[a][5], s[a][6], s[a][7]);
            }
        }
        __syncthreads();
        if (active) {
            // ---- GEMM2: O += P . V ----
#pragma unroll 1
            for (int jg = 0; jg < 16; jg++) {
                int pl = (jg ^ swz) * 4;
                float4 p[8];
#pragma unroll
                for (int a = 0; a < 8; a++)
                    p[a] = *(const float4*)&sP[(ti * 8 + a) * PSTR + pl];
#pragma unroll
                for (int jj = 0; jj < 4; jj++) {
                    int j = jg * 4 + jj;
                    float4 v0 = *(const float4*)&sV[j * KSTR + tj * 8];
                    float4 v1 = *(const float4*)&sV[j * KSTR + tj * 8 + 4];
                    float vv[8] = {v0.x, v0.y, v0.z, v0.w, v1.x, v1.y, v1.z, v1.w};
#pragma unroll
                    for (int a = 0; a < 8; a++) {
                        float pw = (jj == 0) ? p[a].x : (jj == 1) ? p[a].y
                                 : (jj == 2) ? p[a].z : p[a].w;
#pragma unroll
                        for (int b = 0; b < 8; b++) o[a][b] += pw * vv[b];
                    }
                }
            }
        }
    }
    __syncthreads();
    // per-row softmax denominators
#pragma unroll
    for (int a = 0; a < 8; a++) atomicAdd(&sl[ti * 8 + a], lp[a]);
    __syncthreads();
    // normalize + scatter-add
#pragma unroll
    for (int a = 0; a < 8; a++) {
        int i = ti * 8 + a;
        float invl = 1.f / sl[i];
        float* orow = out + ((size_t)bh * Tt + sidx[i]) * Dd + tj * 8;
#pragma unroll
        for (int b = 0; b < 8; b++)
            atomicAdd(orow + b, o[a][b] * invl);
    }
}

// ---------------- kernel 4: divide by count + aux loss ----------------
__global__ void finalize_kernel(float* out, int out_size) {
    const int n = Bq * Hh * Tt * Dd;
    int i = blockIdx.x * blockDim.x + threadIdx.x;
    int stride = gridDim.x * blockDim.x;
    for (int p = i; p < n; p += stride) {
        float cc = (float)g_cnt[p >> 6];
        out[p] = out[p] / (cc + 1e-5f);
    }
    if (i == 0 && out_size > n) {
        out[n] = g_aux * (1e-4f / (float)n);
    }
}

// ---------------- launch ----------------
extern "C" void kernel_launch(void* const* d_in, const int* in_sizes, int n_in,
                              void* d_out, int out_size) {
    const float* q = (const float*)d_in[0];
    const float* k = (const float*)d_in[1];
    const float* v = (const float*)d_in[2];
    const float* means = (const float*)d_in[3];
    float* out = (float*)d_out;

    cudaFuncSetAttribute(attn_kernel, cudaFuncAttributeMaxDynamicSharedMemorySize,
                         ATTN_SMEM_BYTES);

    zero_kernel<<<2048, 256>>>(out, (long long)out_size);
    route_kernel<<<Bq * Hh * Tt / 8, 256>>>(k, means);
    topk_kernel<<<Bq * Hh * NCc, 256>>>();
    attn_kernel<<<Bq * Hh * NCc, 256, ATTN_SMEM_BYTES>>>(q, v, out);
    finalize_kernel<<<2048, 256>>>(out, out_size);
}

// round 3
// speedup vs baseline: 2.2407x; 1.5077x over previous
#include <cuda_runtime.h>
#include <math.h>

#define Bq 4
#define Hh 8
#define Tt 4096
#define Dd 64
#define NCc 16
#define WSZc 256

// ---------------- scratch (no allocations allowed) ----------------
__device__ float g_x[Bq * Hh * Tt * Dd];          // normalized k, 32MB
__device__ float g_dists[Bq * Hh * NCc * Tt];     // [bh, c, t], 8MB
__device__ int   g_idx[Bq * Hh * NCc * WSZc];     // sorted top-k indices
__device__ int   g_cnt[Bq * Hh * Tt];             // scatter counts
__device__ float g_aux;                           // commitment loss sum

// ---------------- kernel 0: zero out / cnt / aux ----------------
__global__ void zero_kernel(float* out, long long n_out) {
    long long i = (long long)blockIdx.x * blockDim.x + threadIdx.x;
    long long stride = (long long)gridDim.x * blockDim.x;
    for (long long p = i; p < n_out; p += stride) out[p] = 0.f;
    for (long long p = i; p < (long long)Bq * Hh * Tt; p += stride) g_cnt[p] = 0;
    if (i == 0) g_aux = 0.f;
}

// ---------------- kernel 1: normalize + dists + argmax + aux ----------------
__global__ void route_kernel(const float* __restrict__ k,
                             const float* __restrict__ means) {
    __shared__ float sm[NCc * Dd];
    __shared__ float saux;
    int token0 = blockIdx.x * 8;
    int bh = token0 / Tt;
    int h = bh % Hh;
    const float* mh = means + (size_t)h * NCc * Dd;
    for (int i = threadIdx.x; i < NCc * Dd; i += blockDim.x) sm[i] = mh[i];
    if (threadIdx.x == 0) saux = 0.f;
    __syncthreads();

    int warp = threadIdx.x >> 5, lane = threadIdx.x & 31;
    int token = token0 + warp;
    int t = token & (Tt - 1);

    float2 kv = ((const float2*)(k + (size_t)token * Dd))[lane];
    float ss = kv.x * kv.x + kv.y * kv.y;
#pragma unroll
    for (int o = 16; o; o >>= 1) ss += __shfl_xor_sync(0xffffffffu, ss, o);
    float inv = rsqrtf(ss);
    float2 xv = make_float2(kv.x * inv, kv.y * inv);
    ((float2*)(g_x + (size_t)token * Dd))[lane] = xv;

    float dl[NCc];
#pragma unroll
    for (int c = 0; c < NCc; c++)
        dl[c] = xv.x * sm[c * Dd + 2 * lane] + xv.y * sm[c * Dd + 2 * lane + 1];
#pragma unroll
    for (int o = 16; o; o >>= 1) {
#pragma unroll
        for (int c = 0; c < NCc; c++)
            dl[c] += __shfl_xor_sync(0xffffffffu, dl[c], o);
    }
    int bestc = 0;
    float bestv = dl[0];
#pragma unroll
    for (int c = 1; c < NCc; c++)
        if (dl[c] > bestv) { bestv = dl[c]; bestc = c; }

    if (lane == 0) {
#pragma unroll
        for (int c = 0; c < NCc; c++)
            g_dists[((size_t)bh * NCc + c) * Tt + t] = dl[c];
    }

    float mx = sm[bestc * Dd + 2 * lane];
    float my = sm[bestc * Dd + 2 * lane + 1];
    float ex = xv.x - mx, ey = xv.y - my;
    float e = ex * ex + ey * ey;
#pragma unroll
    for (int o = 16; o; o >>= 1) e += __shfl_xor_sync(0xffffffffu, e, o);
    if (lane == 0) atomicAdd(&saux, e);
    __syncthreads();
    if (threadIdx.x == 0) atomicAdd(&g_aux, saux);
}

// ---------------- kernel 2: radix-select top-WSZ per (b,h,c) ----------------
__device__ __forceinline__ void find_bin(unsigned* h, unsigned* sscan,
                                         unsigned* s_bin, unsigned* s_k, int tid) {
    unsigned K = *s_k;
    unsigned tot = 0;
#pragma unroll
    for (int r = 0; r < 16; r++) tot += h[tid * 16 + r];
    sscan[tid] = tot;
    __syncthreads();
    for (int off = 1; off < 256; off <<= 1) {
        unsigned vv = (tid + off < 256) ? sscan[tid + off] : 0u;
        __syncthreads();
        sscan[tid] += vv;
        __syncthreads();
    }
    unsigned above = (tid < 255) ? sscan[tid + 1] : 0u;
    unsigned run = above;
#pragma unroll
    for (int r = 15; r >= 0; r--) {
        unsigned c = h[tid * 16 + r];
        run += c;
        if (run >= K && run - c < K) {
            *s_bin = (unsigned)(tid * 16 + r);
            *s_k = K - (run - c);
        }
    }
    __syncthreads();
}

__global__ void __launch_bounds__(256) topk_kernel() {
    __shared__ unsigned su[Tt];
    __shared__ unsigned h[4096];
    __shared__ unsigned sscan[256];
    __shared__ unsigned s_bin, s_k;
    int tid = threadIdx.x;
    int bhc = blockIdx.x;
    const float* dc = g_dists + (size_t)bhc * Tt;

    for (int i = tid; i < Tt; i += 256) {
        unsigned uu = __float_as_uint(dc[i]);
        uu = (uu & 0x80000000u) ? ~uu : (uu | 0x80000000u);
        su[i] = uu;
        h[i] = 0u;
    }
    if (tid == 0) s_k = WSZc;
    __syncthreads();

    for (int i = tid; i < Tt; i += 256) atomicAdd(&h[su[i] >> 20], 1u);
    __syncthreads();
    find_bin(h, sscan, &s_bin, &s_k, tid);
    unsigned b1 = s_bin;
    for (int i = tid; i < 4096; i += 256) h[i] = 0u;
    __syncthreads();

    for (int i = tid; i < Tt; i += 256)
        if ((su[i] >> 20) == b1) atomicAdd(&h[(su[i] >> 8) & 0xFFFu], 1u);
    __syncthreads();
    find_bin(h, sscan, &s_bin, &s_k, tid);
    unsigned b2 = s_bin;
    for (int i = tid; i < 4096; i += 256) h[i] = 0u;
    __syncthreads();

    unsigned hi20 = (b1 << 12) | b2;
    for (int i = tid; i < Tt; i += 256)
        if ((su[i] >> 8) == hi20) atomicAdd(&h[su[i] & 0xFFu], 1u);
    __syncthreads();
    find_bin(h, sscan, &s_bin, &s_k, tid);
    unsigned b3 = s_bin;
    unsigned m = s_k;
    unsigned thr = (b1 << 20) | (b2 << 8) | b3;

    unsigned gt = 0, eq = 0;
    int base = tid * 16;
#pragma unroll
    for (int r = 0; r < 16; r++) {
        unsigned uu = su[base + r];
        gt += (uu > thr);
        eq += (uu == thr);
    }
    unsigned mypack = (gt << 16) | eq;
    sscan[tid] = mypack;
    __syncthreads();
    for (int off = 1; off < 256; off <<= 1) {
        unsigned vv = (tid >= off) ? sscan[tid - off] : 0u;
        __syncthreads();
        sscan[tid] += vv;
        __syncthreads();
    }
    unsigned excl = sscan[tid] - mypack;
    unsigned gtb = excl >> 16, eqb = excl & 0xFFFFu;
    int bh = bhc >> 4;
#pragma unroll
    for (int r = 0; r < 16; r++) {
        unsigned uu = su[base + r];
        if (uu > thr) {
            unsigned emin = eqb < m ? eqb : m;
            int pos = (int)(gtb + emin);
            g_idx[(size_t)bhc * WSZc + pos] = base + r;
            atomicAdd(&g_cnt[bh * Tt + base + r], 1);
            gtb++;
        } else if (uu == thr) {
            if (eqb < m) {
                int pos = (int)(gtb + eqb);
                g_idx[(size_t)bhc * WSZc + pos] = base + r;
                atomicAdd(&g_cnt[bh * Tt + base + r], 1);
            }
            eqb++;
        }
    }
}

// ---------------- kernel 3: tf32 tensor-core windowed attention ----------------
// block = window (256q x 256k x 64d). 8 warps; warp w owns 16-row tiles {w, 15-w}.
// Q/K/V staged in smem pre-permuted to m16n8k8 fragment order.
__device__ __forceinline__ unsigned f2tf(float f) {
    unsigned u;
    asm("cvt.rna.tf32.f32 %0, %1;" : "=r"(u) : "f"(f));
    return u;
}
__device__ __forceinline__ void mma8(float& d0, float& d1, float& d2, float& d3,
                                     unsigned a0, unsigned a1, unsigned a2, unsigned a3,
                                     unsigned b0, unsigned b1) {
    asm volatile("mma.sync.aligned.m16n8k8.row.col.f32.tf32.tf32.f32 "
                 "{%0,%1,%2,%3}, {%4,%5,%6,%7}, {%8,%9}, {%0,%1,%2,%3};"
                 : "+f"(d0), "+f"(d1), "+f"(d2), "+f"(d3)
                 : "r"(a0), "r"(a1), "r"(a2), "r"(a3), "r"(b0), "r"(b1));
}

#define PT_STR 68
#define QF_SZ (16 * 8 * 32 * 4)      // 16384 u32
#define KF_SZ (8 * 8 * 32 * 2)       // 4096
#define VF_SZ (8 * 8 * 32 * 2)       // 4096
#define PF_SZ (16 * 16 * PT_STR)     // 17408
#define ATTN_SMEM_BYTES ((QF_SZ + KF_SZ + VF_SZ + PF_SZ) * 4)

__global__ void __launch_bounds__(256, 1) attn_kernel(const float* __restrict__ q,
                                                      const float* __restrict__ v,
                                                      float* __restrict__ out) {
    extern __shared__ unsigned smu[];
    unsigned* QF = smu;
    unsigned* KF = smu + QF_SZ;
    unsigned* VF = smu + QF_SZ + KF_SZ;
    unsigned* PF = smu + QF_SZ + KF_SZ + VF_SZ;
    __shared__ int sidx[WSZc];

    int tid = threadIdx.x;
    int bhc = blockIdx.x;
    int bh = bhc >> 4;
    int w = tid >> 5, lane = tid & 31;
    int g = lane >> 2, c = lane & 3;

    sidx[tid] = g_idx[(size_t)bhc * WSZc + tid];
    __syncthreads();

    // ---- stage Q into A-fragment order (tf32) ----
    {
        int gi = sidx[tid];
        const float4* qs = (const float4*)(q + ((size_t)bh * Tt + gi) * Dd);
        int tile = tid >> 4, r16 = tid & 15;
        int gq = r16 & 7, halfm = r16 >> 3;
#pragma unroll
        for (int rr = 0; rr < 16; rr++) {
            float4 a = qs[rr];
            int d0 = rr * 4;
            int ks = d0 >> 3, halfk = (d0 >> 2) & 1;
            int reg = halfm + 2 * halfk;
            unsigned idx0 = (unsigned)(((tile * 8 + ks) * 32 + gq * 4) * 4 + reg);
            QF[idx0 + 0] = f2tf(a.x);
            QF[idx0 + 4] = f2tf(a.y);
            QF[idx0 + 8] = f2tf(a.z);
            QF[idx0 + 12] = f2tf(a.w);
        }
    }

    int tw0 = w, tw1 = 15 - w;
    float O[2][8][4];
#pragma unroll
    for (int m = 0; m < 2; m++)
#pragma unroll
        for (int nt = 0; nt < 8; nt++)
#pragma unroll
            for (int r = 0; r < 4; r++) O[m][nt][r] = 0.f;
    float lp[2][2] = {{0.f, 0.f}, {0.f, 0.f}};

    for (int jc = 0; jc < 4; jc++) {
        __syncthreads();
        // ---- stage K chunk (B-frag for GEMM1) + V chunk (B-frag for GEMM2) ----
        {
            int r = tid >> 2, part = tid & 3;
            int gj = sidx[jc * 64 + r];
            const float4* xs = (const float4*)(g_x + ((size_t)bh * Tt + gj) * Dd) + part * 4;
            const float4* vs = (const float4*)(v + ((size_t)bh * Tt + gj) * Dd) + part * 4;
            int gk = r & 7, nt = r >> 3;                    // K: j is n-dim
            int ks2 = r >> 3, c0v = r & 3, halfv = (r >> 2) & 1;  // V: j is k-dim
#pragma unroll
            for (int e4 = 0; e4 < 4; e4++) {
                float4 kk = xs[e4];
                float4 vv = vs[e4];
                int d0 = part * 16 + e4 * 4;
                // K frag: (ks = d0>>3, half = (d0>>2)&1), lane = gk*4 + (d&3)
                {
                    int ks = d0 >> 3, half = (d0 >> 2) & 1;
                    unsigned base = (unsigned)(((ks * 8 + nt) * 32 + gk * 4) * 2 + half);
                    KF[base + 0] = f2tf(kk.x);
                    KF[base + 2] = f2tf(kk.y);
                    KF[base + 4] = f2tf(kk.z);
                    KF[base + 6] = f2tf(kk.w);
                }
                // V frag: nt2 = d0>>3, gv = (d0&7)+e, lane = gv*4 + c0v
                {
                    int nt2 = d0 >> 3;
                    unsigned base = (unsigned)(((ks2 * 8 + nt2) * 32 + (d0 & 7) * 4 + c0v) * 2 + halfv);
                    VF[base + 0] = f2tf(vv.x);
                    VF[base + 8] = f2tf(vv.y);
                    VF[base + 16] = f2tf(vv.z);
                    VF[base + 24] = f2tf(vv.w);
                }
            }
        }
        __syncthreads();

        // ---- GEMM1: S = Q . K^T, mask, exp, store P frags ----
#pragma unroll
        for (int m = 0; m < 2; m++) {
            int t = (m == 0) ? tw0 : tw1;
            if (4 * jc > t) continue;
            unsigned a[8][4];
#pragma unroll
            for (int ks = 0; ks < 8; ks++)
                *(uint4*)a[ks] = *(const uint4*)&QF[((t * 8 + ks) * 32 + lane) * 4];
            unsigned pb = (unsigned)(t * (16 * PT_STR));
#pragma unroll
            for (int nt = 0; nt < 8; nt++) {
                if (8 * jc + nt > 2 * t + 1) continue;
                float s0 = 0.f, s1 = 0.f, s2 = 0.f, s3 = 0.f;
#pragma unroll
                for (int ks = 0; ks < 8; ks++) {
                    uint2 b = *(const uint2*)&KF[((ks * 8 + nt) * 32 + lane) * 2];
                    mma8(s0, s1, s2, s3, a[ks][0], a[ks][1], a[ks][2], a[ks][3], b.x, b.y);
                }
                int i0 = 16 * t + g, i1 = i0 + 8;
                int j0 = 64 * jc + 8 * nt + 2 * c, j1 = j0 + 1;
                float p00, p01, p10, p11;
                p00 = (j0 > i0) ? 0.f : (j0 == i0) ? ((i0 == 0) ? 1.f : 0.f) : __expf(s0 * 0.125f);
                p01 = (j1 > i0) ? 0.f : (j1 == i0) ? 0.f : __expf(s1 * 0.125f);
                p10 = (j0 > i1) ? 0.f : (j0 == i1) ? 0.f : __expf(s2 * 0.125f);
                p11 = (j1 > i1) ? 0.f : (j1 == i1) ? 0.f : __expf(s3 * 0.125f);
                lp[m][0] += p00 + p01;
                lp[m][1] += p10 + p11;
                uint2 st0 = make_uint2(f2tf(p00), f2tf(p01));
                uint2 st1 = make_uint2(f2tf(p10), f2tf(p11));
                *(uint2*)&PF[pb + g * PT_STR + 8 * nt + 2 * c] = st0;
                *(uint2*)&PF[pb + (g + 8) * PT_STR + 8 * nt + 2 * c] = st1;
            }
        }
        __syncwarp();

        // ---- GEMM2: O += P . V ----
#pragma unroll
        for (int m = 0; m < 2; m++) {
            int t = (m == 0) ? tw0 : tw1;
            if (4 * jc > t) continue;
            unsigned pb = (unsigned)(t * (16 * PT_STR));
#pragma unroll
            for (int ks2 = 0; ks2 < 8; ks2++) {
                if (8 * jc + ks2 > 2 * t + 1) continue;
                unsigned pa0 = PF[pb + g * PT_STR + 8 * ks2 + c];
                unsigned pa1 = PF[pb + (g + 8) * PT_STR + 8 * ks2 + c];
                unsigned pa2 = PF[pb + g * PT_STR + 8 * ks2 + c + 4];
                unsigned pa3 = PF[pb + (g + 8) * PT_STR + 8 * ks2 + c + 4];
#pragma unroll
                for (int nt2 = 0; nt2 < 8; nt2++) {
                    uint2 bv = *(const uint2*)&VF[((ks2 * 8 + nt2) * 32 + lane) * 2];
                    mma8(O[m][nt2][0], O[m][nt2][1], O[m][nt2][2], O[m][nt2][3],
                         pa0, pa1, pa2, pa3, bv.x, bv.y);
                }
            }
        }
        __syncwarp();
    }

    // ---- row sums across the 4 lanes sharing a row, then normalize+scatter ----
    float rs[2][2];
#pragma unroll
    for (int m = 0; m < 2; m++)
#pragma unroll
        for (int hf = 0; hf < 2; hf++) {
            float s = lp[m][hf];
            s += __shfl_xor_sync(0xffffffffu, s, 1);
            s += __shfl_xor_sync(0xffffffffu, s, 2);
            rs[m][hf] = 1.f / s;
        }
#pragma unroll
    for (int m = 0; m < 2; m++) {
        int t = (m == 0) ? tw0 : tw1;
        int i0 = 16 * t + g, i1 = i0 + 8;
        float* o0 = out + ((size_t)bh * Tt + sidx[i0]) * Dd;
        float* o1 = out + ((size_t)bh * Tt + sidx[i1]) * Dd;
#pragma unroll
        for (int nt2 = 0; nt2 < 8; nt2++) {
            int col = 8 * nt2 + 2 * c;
            atomicAdd(o0 + col, O[m][nt2][0] * rs[m][0]);
            atomicAdd(o0 + col + 1, O[m][nt2][1] * rs[m][0]);
            atomicAdd(o1 + col, O[m][nt2][2] * rs[m][1]);
            atomicAdd(o1 + col + 1, O[m][nt2][3] * rs[m][1]);
        }
    }
}

// ---------------- kernel 4: divide by count + aux loss ----------------
__global__ void finalize_kernel(float* out, int out_size) {
    const int n = Bq * Hh * Tt * Dd;
    int i = blockIdx.x * blockDim.x + threadIdx.x;
    int stride = gridDim.x * blockDim.x;
    for (int p = i; p < n; p += stride) {
        float cc = (float)g_cnt[p >> 6];
        out[p] = out[p] / (cc + 1e-5f);
    }
    if (i == 0 && out_size > n) {
        out[n] = g_aux * (1e-4f / (float)n);
    }
}

// ---------------- launch ----------------
extern "C" void kernel_launch(void* const* d_in, const int* in_sizes, int n_in,
                              void* d_out, int out_size) {
    const float* q = (const float*)d_in[0];
    const float* k = (const float*)d_in[1];
    const float* v = (const float*)d_in[2];
    const float* means = (const float*)d_in[3];
    float* out = (float*)d_out;

    cudaFuncSetAttribute(attn_kernel, cudaFuncAttributeMaxDynamicSharedMemorySize,
                         ATTN_SMEM_BYTES);

    zero_kernel<<<2048, 256>>>(out, (long long)out_size);
    route_kernel<<<Bq * Hh * Tt / 8, 256>>>(k, means);
    topk_kernel<<<Bq * Hh * NCc, 256>>>();
    attn_kernel<<<Bq * Hh * NCc, 256, ATTN_SMEM_BYTES>>>(q, v, out);
    finalize_kernel<<<2048, 256>>>(out, out_size);
}

// round 6
// speedup vs baseline: 2.5549x; 1.1402x over previous
#include <cuda_runtime.h>
#include <math.h>

#define Bq 4
#define Hh 8
#define Tt 4096
#define Dd 64
#define NCc 16
#define WSZc 256

// ---------------- scratch (no allocations allowed) ----------------
__device__ float g_x[Bq * Hh * Tt * Dd];          // normalized k, 32MB
__device__ float g_dists[Bq * Hh * NCc * Tt];     // [bh, c, t], 8MB
__device__ int   g_idx[Bq * Hh * NCc * WSZc];     // sorted top-k indices
__device__ int   g_cnt[Bq * Hh * Tt];             // scatter counts
__device__ float g_aux_part[Bq * Hh * Tt / 8];    // per-route-block aux partials

// ---------------- kernel 1: route (+ zero out/cnt) ----------------
__global__ void route_kernel(const float* __restrict__ k,
                             const float* __restrict__ means,
                             float* __restrict__ out) {
    __shared__ float sm[NCc * Dd];
    __shared__ float saux;
    __shared__ float sdl[NCc][8];

    // fold in zeroing of out + cnt (completes before topk/attn kernels run)
    {
        long long gid = (long long)blockIdx.x * blockDim.x + threadIdx.x;
        long long gtot = (long long)gridDim.x * blockDim.x;
        const long long n4 = (long long)Bq * Hh * Tt * Dd / 4;
        for (long long p = gid; p < n4; p += gtot)
            ((float4*)out)[p] = make_float4(0.f, 0.f, 0.f, 0.f);
        const long long c4 = (long long)Bq * Hh * Tt / 4;
        for (long long p = gid; p < c4; p += gtot)
            ((int4*)g_cnt)[p] = make_int4(0, 0, 0, 0);
    }

    int token0 = blockIdx.x * 8;
    int bh = token0 / Tt;
    int h = bh % Hh;
    const float* mh = means + (size_t)h * NCc * Dd;
    for (int i = threadIdx.x; i < NCc * Dd; i += blockDim.x) sm[i] = mh[i];
    if (threadIdx.x == 0) saux = 0.f;
    __syncthreads();

    int warp = threadIdx.x >> 5, lane = threadIdx.x & 31;
    int token = token0 + warp;
    int t = token & (Tt - 1);

    float2 kv = ((const float2*)(k + (size_t)token * Dd))[lane];
    float ss = kv.x * kv.x + kv.y * kv.y;
#pragma unroll
    for (int o = 16; o; o >>= 1) ss += __shfl_xor_sync(0xffffffffu, ss, o);
    float inv = rsqrtf(ss);
    float2 xv = make_float2(kv.x * inv, kv.y * inv);
    ((float2*)(g_x + (size_t)token * Dd))[lane] = xv;

    float dl[NCc];
#pragma unroll
    for (int c = 0; c < NCc; c++)
        dl[c] = xv.x * sm[c * Dd + 2 * lane] + xv.y * sm[c * Dd + 2 * lane + 1];
#pragma unroll
    for (int o = 16; o; o >>= 1) {
#pragma unroll
        for (int c = 0; c < NCc; c++)
            dl[c] += __shfl_xor_sync(0xffffffffu, dl[c], o);
    }
    int bestc = 0;
    float bestv = dl[0];
#pragma unroll
    for (int c = 1; c < NCc; c++)
        if (dl[c] > bestv) { bestv = dl[c]; bestc = c; }

    if (lane == 0) {
#pragma unroll
        for (int c = 0; c < NCc; c++) sdl[c][warp] = dl[c];
    }

    float mx = sm[bestc * Dd + 2 * lane];
    float my = sm[bestc * Dd + 2 * lane + 1];
    float ex = xv.x - mx, ey = xv.y - my;
    float e = ex * ex + ey * ey;
#pragma unroll
    for (int o = 16; o; o >>= 1) e += __shfl_xor_sync(0xffffffffu, e, o);
    if (lane == 0) atomicAdd(&saux, e);
    __syncthreads();

    // coalesced g_dists store: 16 rows x 8 consecutive t
    if (threadIdx.x < 128) {
        int c = threadIdx.x >> 3, tt = threadIdx.x & 7;
        int tbase = token0 & (Tt - 1);
        g_dists[((size_t)bh * NCc + c) * Tt + tbase + tt] = sdl[c][tt];
    }
    if (threadIdx.x == 0) g_aux_part[blockIdx.x] = saux;
}

// ---------------- kernel 2: radix-select top-WSZ per (b,h,c) ----------------
__device__ __forceinline__ unsigned warp_incl_scan(unsigned v, int lane) {
#pragma unroll
    for (int off = 1; off < 32; off <<= 1) {
        unsigned t = __shfl_up_sync(0xffffffffu, v, off);
        if (lane >= off) v += t;
    }
    return v;
}

__device__ __forceinline__ void find_bin(unsigned* h, unsigned* wsum,
                                         unsigned* s_bin, unsigned* s_k, int tid) {
    int lane = tid & 31, w = tid >> 5;
    unsigned K = *s_k;
    unsigned tot = 0;
#pragma unroll
    for (int r = 0; r < 16; r++) tot += h[tid * 16 + r];
    unsigned p = warp_incl_scan(tot, lane);
    if (lane == 31) wsum[w] = p;
    __syncthreads();
    unsigned off = 0, S = 0;
#pragma unroll
    for (int i = 0; i < 8; i++) {
        unsigned x = wsum[i];
        S += x;
        if (i < w) off += x;
    }
    unsigned above = S - (p + off);  // sum over strictly-higher threads
    unsigned run = above;
#pragma unroll
    for (int r = 15; r >= 0; r--) {
        unsigned cc = h[tid * 16 + r];
        run += cc;
        if (run >= K && run - cc < K) {
            *s_bin = (unsigned)(tid * 16 + r);
            *s_k = K - (run - cc);
        }
    }
    __syncthreads();
}

__global__ void __launch_bounds__(256) topk_kernel() {
    __shared__ unsigned su[Tt];
    __shared__ unsigned h[4096];
    __shared__ unsigned wsum[8];
    __shared__ unsigned s_bin, s_k;
    int tid = threadIdx.x;
    int lane = tid & 31, w = tid >> 5;
    int bhc = blockIdx.x;
    const float* dc = g_dists + (size_t)bhc * Tt;

    for (int i = tid; i < Tt; i += 256) {
        unsigned uu = __float_as_uint(dc[i]);
        uu = (uu & 0x80000000u) ? ~uu : (uu | 0x80000000u);
        su[i] = uu;
        h[i] = 0u;
    }
    if (tid == 0) s_k = WSZc;
    __syncthreads();

    for (int i = tid; i < Tt; i += 256) atomicAdd(&h[su[i] >> 20], 1u);
    __syncthreads();
    find_bin(h, wsum, &s_bin, &s_k, tid);
    unsigned b1 = s_bin;
    for (int i = tid; i < 4096; i += 256) h[i] = 0u;
    __syncthreads();

    for (int i = tid; i < Tt; i += 256)
        if ((su[i] >> 20) == b1) atomicAdd(&h[(su[i] >> 8) & 0xFFFu], 1u);
    __syncthreads();
    find_bin(h, wsum, &s_bin, &s_k, tid);
    unsigned b2 = s_bin;
    for (int i = tid; i < 4096; i += 256) h[i] = 0u;
    __syncthreads();

    unsigned hi20 = (b1 << 12) | b2;
    for (int i = tid; i < Tt; i += 256)
        if ((su[i] >> 8) == hi20) atomicAdd(&h[su[i] & 0xFFu], 1u);
    __syncthreads();
    find_bin(h, wsum, &s_bin, &s_k, tid);
    unsigned b3 = s_bin;
    unsigned m = s_k;
    unsigned thr = (b1 << 20) | (b2 << 8) | b3;

    // ordered compaction over contiguous 16-element runs per thread
    unsigned gt = 0, eq = 0;
    int base = tid * 16;
#pragma unroll
    for (int r = 0; r < 16; r++) {
        unsigned uu = su[base + r];
        gt += (uu > thr);
        eq += (uu == thr);
    }
    unsigned mypack = (gt << 16) | eq;
    unsigned p = warp_incl_scan(mypack, lane);
    if (lane == 31) wsum[w] = p;
    __syncthreads();
    unsigned off = 0;
#pragma unroll
    for (int i = 0; i < 8; i++)
        if (i < w) off += wsum[i];
    unsigned excl = p + off - mypack;
    unsigned gtb = excl >> 16, eqb = excl & 0xFFFFu;
    int bh = bhc >> 4;
#pragma unroll
    for (int r = 0; r < 16; r++) {
        unsigned uu = su[base + r];
        if (uu > thr) {
            unsigned emin = eqb < m ? eqb : m;
            int pos = (int)(gtb + emin);
            g_idx[(size_t)bhc * WSZc + pos] = base + r;
            atomicAdd(&g_cnt[bh * Tt + base + r], 1);
            gtb++;
        } else if (uu == thr) {
            if (eqb < m) {
                int pos = (int)(gtb + eqb);
                g_idx[(size_t)bhc * WSZc + pos] = base + r;
                atomicAdd(&g_cnt[bh * Tt + base + r], 1);
            }
            eqb++;
        }
    }
}

// ---------------- kernel 3: tf32 tensor-core windowed attention ----------------
__device__ __forceinline__ unsigned f2tf(float f) {
    unsigned u;
    asm("cvt.rna.tf32.f32 %0, %1;" : "=r"(u) : "f"(f));
    return u;
}
__device__ __forceinline__ void mma8(float* d, const unsigned* a, uint2 b) {
    asm volatile("mma.sync.aligned.m16n8k8.row.col.f32.tf32.tf32.f32 "
                 "{%0,%1,%2,%3}, {%4,%5,%6,%7}, {%8,%9}, {%0,%1,%2,%3};"
                 : "+f"(d[0]), "+f"(d[1]), "+f"(d[2]), "+f"(d[3])
                 : "r"(a[0]), "r"(a[1]), "r"(a[2]), "r"(a[3]), "r"(b.x), "r"(b.y));
}

#define PT_STR 68
#define KF_SZ (8 * 8 * 32 * 2)       // 4096 u32
#define VF_SZ (8 * 8 * 32 * 2)       // 4096
#define PF_SZ (16 * 16 * PT_STR)     // 17408
#define ATTN_SMEM_BYTES ((KF_SZ + VF_SZ + PF_SZ) * 4)

// mask + exp + P-store + rowsum for one 16x8 score tile
__device__ __forceinline__ void epi_tile(unsigned* PF, int t, int jc, int nt,
                                         int g, int c, const float* s,
                                         float& l0, float& l1) {
    int i0 = 16 * t + g, i1 = i0 + 8;
    int j0 = 64 * jc + 8 * nt + 2 * c, j1 = j0 + 1;
    float p00 = (j0 > i0) ? 0.f : (j0 == i0) ? ((i0 == 0) ? 1.f : 0.f) : __expf(s[0] * 0.125f);
    float p01 = (j1 > i0) ? 0.f : (j1 == i0) ? 0.f : __expf(s[1] * 0.125f);
    float p10 = (j0 > i1) ? 0.f : (j0 == i1) ? 0.f : __expf(s[2] * 0.125f);
    float p11 = (j1 > i1) ? 0.f : (j1 == i1) ? 0.f : __expf(s[3] * 0.125f);
    l0 += p00 + p01;
    l1 += p10 + p11;
    unsigned pb = (unsigned)(t * (16 * PT_STR));
    *(uint2*)&PF[pb + g * PT_STR + 8 * nt + 2 * c] = make_uint2(f2tf(p00), f2tf(p01));
    *(uint2*)&PF[pb + (g + 8) * PT_STR + 8 * nt + 2 * c] = make_uint2(f2tf(p10), f2tf(p11));
}

__global__ void __launch_bounds__(256, 1) attn_kernel(const float* __restrict__ q,
                                                      const float* __restrict__ v,
                                                      float* __restrict__ out) {
    extern __shared__ unsigned smu[];
    unsigned* KF = smu;
    unsigned* VF = smu + KF_SZ;
    unsigned* PF = smu + KF_SZ + VF_SZ;
    __shared__ int sidx[WSZc];

    int tid = threadIdx.x;
    int bhc = blockIdx.x;
    int bh = bhc >> 4;
    int w = tid >> 5, lane = tid & 31;
    int g = lane >> 2, c = lane & 3;
    int t0 = w, t1 = 15 - w;   // t1 > t0 always

    sidx[tid] = g_idx[(size_t)bhc * WSZc + tid];
    __syncthreads();

    // ---- Q A-fragments directly into registers (held across all chunks) ----
    unsigned A0[8][4], A1[8][4];
    {
        const float* qb = q + (size_t)bh * Tt * Dd;
        const float* r00 = qb + (size_t)sidx[16 * t0 + g] * Dd;
        const float* r01 = qb + (size_t)sidx[16 * t0 + g + 8] * Dd;
        const float* r10 = qb + (size_t)sidx[16 * t1 + g] * Dd;
        const float* r11 = qb + (size_t)sidx[16 * t1 + g + 8] * Dd;
#pragma unroll
        for (int ks = 0; ks < 8; ks++) {
            A0[ks][0] = f2tf(r00[8 * ks + c]);
            A0[ks][1] = f2tf(r01[8 * ks + c]);
            A0[ks][2] = f2tf(r00[8 * ks + c + 4]);
            A0[ks][3] = f2tf(r01[8 * ks + c + 4]);
            A1[ks][0] = f2tf(r10[8 * ks + c]);
            A1[ks][1] = f2tf(r11[8 * ks + c]);
            A1[ks][2] = f2tf(r10[8 * ks + c + 4]);
            A1[ks][3] = f2tf(r11[8 * ks + c + 4]);
        }
    }

    float O0[8][4], O1[8][4];
#pragma unroll
    for (int nt = 0; nt < 8; nt++)
#pragma unroll
        for (int r = 0; r < 4; r++) { O0[nt][r] = 0.f; O1[nt][r] = 0.f; }
    float lp0[2] = {0.f, 0.f}, lp1[2] = {0.f, 0.f};

    for (int jc = 0; jc < 4; jc++) {
        __syncthreads();
        // ---- stage K/V chunk into B-fragment order ----
        {
            int r = tid >> 2, part = tid & 3;
            int gj = sidx[jc * 64 + r];
            const float4* xs = (const float4*)(g_x + ((size_t)bh * Tt + gj) * Dd) + part * 4;
            const float4* vs = (const float4*)(v + ((size_t)bh * Tt + gj) * Dd) + part * 4;
            int gk = r & 7, nt = r >> 3;
            int ks2 = r >> 3, c0v = r & 3, halfv = (r >> 2) & 1;
#pragma unroll
            for (int e4 = 0; e4 < 4; e4++) {
                float4 kk = xs[e4];
                float4 vv = vs[e4];
                int d0 = part * 16 + e4 * 4;
                {
                    int ks = d0 >> 3, half = (d0 >> 2) & 1;
                    unsigned base = (unsigned)(((ks * 8 + nt) * 32 + gk * 4) * 2 + half);
                    KF[base + 0] = f2tf(kk.x);
                    KF[base + 2] = f2tf(kk.y);
                    KF[base + 4] = f2tf(kk.z);
                    KF[base + 6] = f2tf(kk.w);
                }
                {
                    int nt2 = d0 >> 3;
                    unsigned base = (unsigned)(((ks2 * 8 + nt2) * 32 + (d0 & 7) * 4 + c0v) * 2 + halfv);
                    VF[base + 0] = f2tf(vv.x);
                    VF[base + 8] = f2tf(vv.y);
                    VF[base + 16] = f2tf(vv.z);
                    VF[base + 24] = f2tf(vv.w);
                }
            }
        }
        __syncthreads();

        int lim0 = 2 * t0 + 1 - 8 * jc;   // tile0 needs nt <= lim0
        int lim1 = 2 * t1 + 1 - 8 * jc;   // tile1 needs nt <= lim1 (lim1 >= lim0)

        // ---- GEMM1: S = Q . K^T (B frags shared across both tiles) ----
#pragma unroll
        for (int nt = 0; nt < 8; nt++) {
            if (nt > lim1) break;
            bool need0 = (nt <= lim0);
            float s1v[4] = {0.f, 0.f, 0.f, 0.f};
            float s0v[4] = {0.f, 0.f, 0.f, 0.f};
#pragma unroll
            for (int ks = 0; ks < 8; ks++) {
                uint2 b = *(const uint2*)&KF[((ks * 8 + nt) * 32 + lane) * 2];
                mma8(s1v, A1[ks], b);
                if (need0) mma8(s0v, A0[ks], b);
            }
            epi_tile(PF, t1, jc, nt, g, c, s1v, lp1[0], lp1[1]);
            if (need0) epi_tile(PF, t0, jc, nt, g, c, s0v, lp0[0], lp0[1]);
        }
        __syncwarp();

        // ---- GEMM2: O += P . V (V frags shared across both tiles) ----
        unsigned pb0 = (unsigned)(t0 * (16 * PT_STR));
        unsigned pb1 = (unsigned)(t1 * (16 * PT_STR));
#pragma unroll
        for (int ks2 = 0; ks2 < 8; ks2++) {
            if (ks2 > lim1) break;
            bool need0 = (ks2 <= lim0);
            unsigned p1[4], p0[4];
            p1[0] = PF[pb1 + g * PT_STR + 8 * ks2 + c];
            p1[1] = PF[pb1 + (g + 8) * PT_STR + 8 * ks2 + c];
            p1[2] = PF[pb1 + g * PT_STR + 8 * ks2 + c + 4];
            p1[3] = PF[pb1 + (g + 8) * PT_STR + 8 * ks2 + c + 4];
            if (need0) {
                p0[0] = PF[pb0 + g * PT_STR + 8 * ks2 + c];
                p0[1] = PF[pb0 + (g + 8) * PT_STR + 8 * ks2 + c];
                p0[2] = PF[pb0 + g * PT_STR + 8 * ks2 + c + 4];
                p0[3] = PF[pb0 + (g + 8) * PT_STR + 8 * ks2 + c + 4];
            }
#pragma unroll
            for (int nt2 = 0; nt2 < 8; nt2++) {
                uint2 bv = *(const uint2*)&VF[((ks2 * 8 + nt2) * 32 + lane) * 2];
                mma8(O1[nt2], p1, bv);
                if (need0) mma8(O0[nt2], p0, bv);
            }
        }
        __syncwarp();
    }

    // ---- row-sum reduce across 4 lanes of the row, normalize, scatter ----
    float rs0[2], rs1[2];
#pragma unroll
    for (int hf = 0; hf < 2; hf++) {
        float s = lp0[hf];
        s += __shfl_xor_sync(0xffffffffu, s, 1);
        s += __shfl_xor_sync(0xffffffffu, s, 2);
        rs0[hf] = 1.f / s;
        s = lp1[hf];
        s += __shfl_xor_sync(0xffffffffu, s, 1);
        s += __shfl_xor_sync(0xffffffffu, s, 2);
        rs1[hf] = 1.f / s;
    }
    {
        float* ob = out + (size_t)bh * Tt * Dd;
        float* o00 = ob + (size_t)sidx[16 * t0 + g] * Dd;
        float* o01 = ob + (size_t)sidx[16 * t0 + g + 8] * Dd;
        float* o10 = ob + (size_t)sidx[16 * t1 + g] * Dd;
        float* o11 = ob + (size_t)sidx[16 * t1 + g + 8] * Dd;
#pragma unroll
        for (int nt2 = 0; nt2 < 8; nt2++) {
            int col = 8 * nt2 + 2 * c;
            atomicAdd(o00 + col, O0[nt2][0] * rs0[0]);
            atomicAdd(o00 + col + 1, O0[nt2][1] * rs0[0]);
            atomicAdd(o01 + col, O0[nt2][2] * rs0[1]);
            atomicAdd(o01 + col + 1, O0[nt2][3] * rs0[1]);
            atomicAdd(o10 + col, O1[nt2][0] * rs1[0]);
            atomicAdd(o10 + col + 1, O1[nt2][1] * rs1[0]);
            atomicAdd(o11 + col, O1[nt2][2] * rs1[1]);
            atomicAdd(o11 + col + 1, O1[nt2][3] * rs1[1]);
        }
    }
}

// ---------------- kernel 4: divide by count + aux loss ----------------
__global__ void finalize_kernel(float* out, int out_size) {
    const int n = Bq * Hh * Tt * Dd;
    const int n4 = n / 4;
    int i = blockIdx.x * blockDim.x + threadIdx.x;
    int stride = gridDim.x * blockDim.x;
    for (int p = i; p < n4; p += stride) {
        float4 o = ((float4*)out)[p];
        float cc = (float)g_cnt[p >> 4];
        float inv = 1.f / (cc + 1e-5f);
        o.x *= inv; o.y *= inv; o.z *= inv; o.w *= inv;
        ((float4*)out)[p] = o;
    }
    if (blockIdx.x == 0) {
        __shared__ float sred[256];
        float s = 0.f;
        for (int p = threadIdx.x; p < Bq * Hh * Tt / 8; p += 256) s += g_aux_part[p];
        sred[threadIdx.x] = s;
        __syncthreads();
        for (int off = 128; off; off >>= 1) {
            if (threadIdx.x < off) sred[threadIdx.x] += sred[threadIdx.x + off];
            __syncthreads();
        }
        if (threadIdx.x == 0 && out_size > n)
            out[n] = sred[0] * (1e-4f / (float)n);
    }
}

// ---------------- launch ----------------
extern "C" void kernel_launch(void* const* d_in, const int* in_sizes, int n_in,
                              void* d_out, int out_size) {
    const float* q = (const float*)d_in[0];
    const float* k = (const float*)d_in[1];
    const float* v = (const float*)d_in[2];
    const float* means = (const float*)d_in[3];
    float* out = (float*)d_out;

    cudaFuncSetAttribute(attn_kernel, cudaFuncAttributeMaxDynamicSharedMemorySize,
                         ATTN_SMEM_BYTES);

    route_kernel<<<Bq * Hh * Tt / 8, 256>>>(k, means, out);
    topk_kernel<<<Bq * Hh * NCc, 256>>>();
    attn_kernel<<<Bq * Hh * NCc, 256, ATTN_SMEM_BYTES>>>(q, v, out);
    finalize_kernel<<<2048, 256>>>(out, out_size);
}

// round 7
// speedup vs baseline: 2.5761x; 1.0083x over previous
#include <cuda_runtime.h>
#include <math.h>

#define Bq 4
#define Hh 8
#define Tt 4096
#define Dd 64
#define NCc 16
#define WSZc 256

// ---------------- scratch (no allocations allowed) ----------------
__device__ float g_x[Bq * Hh * Tt * Dd];          // normalized k, 32MB
__device__ float g_dists[Bq * Hh * NCc * Tt];     // [bh, c, t], 8MB
__device__ int   g_idx[Bq * Hh * NCc * WSZc];     // sorted top-k indices
__device__ int   g_cnt[Bq * Hh * Tt];             // scatter counts
__device__ float g_aux_part[Bq * Hh * Tt / 8];    // per-route-block aux partials

// ---------------- kernel 1: route (+ zero out/cnt) ----------------
__global__ void route_kernel(const float* __restrict__ k,
                             const float* __restrict__ means,
                             float* __restrict__ out) {
    __shared__ float sm[NCc * Dd];
    __shared__ float saux;
    __shared__ float sdl[NCc][8];

    {
        long long gid = (long long)blockIdx.x * blockDim.x + threadIdx.x;
        long long gtot = (long long)gridDim.x * blockDim.x;
        const long long n4 = (long long)Bq * Hh * Tt * Dd / 4;
        for (long long p = gid; p < n4; p += gtot)
            ((float4*)out)[p] = make_float4(0.f, 0.f, 0.f, 0.f);
        const long long c4 = (long long)Bq * Hh * Tt / 4;
        for (long long p = gid; p < c4; p += gtot)
            ((int4*)g_cnt)[p] = make_int4(0, 0, 0, 0);
    }

    int token0 = blockIdx.x * 8;
    int bh = token0 / Tt;
    int h = bh % Hh;
    const float* mh = means + (size_t)h * NCc * Dd;
    for (int i = threadIdx.x; i < NCc * Dd; i += blockDim.x) sm[i] = mh[i];
    if (threadIdx.x == 0) saux = 0.f;
    __syncthreads();

    int warp = threadIdx.x >> 5, lane = threadIdx.x & 31;
    int token = token0 + warp;
    int t = token & (Tt - 1);

    float2 kv = ((const float2*)(k + (size_t)token * Dd))[lane];
    float ss = kv.x * kv.x + kv.y * kv.y;
#pragma unroll
    for (int o = 16; o; o >>= 1) ss += __shfl_xor_sync(0xffffffffu, ss, o);
    float inv = rsqrtf(ss);
    float2 xv = make_float2(kv.x * inv, kv.y * inv);
    ((float2*)(g_x + (size_t)token * Dd))[lane] = xv;

    float dl[NCc];
#pragma unroll
    for (int c = 0; c < NCc; c++)
        dl[c] = xv.x * sm[c * Dd + 2 * lane] + xv.y * sm[c * Dd + 2 * lane + 1];
#pragma unroll
    for (int o = 16; o; o >>= 1) {
#pragma unroll
        for (int c = 0; c < NCc; c++)
            dl[c] += __shfl_xor_sync(0xffffffffu, dl[c], o);
    }
    int bestc = 0;
    float bestv = dl[0];
#pragma unroll
    for (int c = 1; c < NCc; c++)
        if (dl[c] > bestv) { bestv = dl[c]; bestc = c; }

    if (lane == 0) {
#pragma unroll
        for (int c = 0; c < NCc; c++) sdl[c][warp] = dl[c];
    }

    float mx = sm[bestc * Dd + 2 * lane];
    float my = sm[bestc * Dd + 2 * lane + 1];
    float ex = xv.x - mx, ey = xv.y - my;
    float e = ex * ex + ey * ey;
#pragma unroll
    for (int o = 16; o; o >>= 1) e += __shfl_xor_sync(0xffffffffu, e, o);
    if (lane == 0) atomicAdd(&saux, e);
    __syncthreads();

    if (threadIdx.x < 128) {
        int c = threadIdx.x >> 3, tt = threadIdx.x & 7;
        int tbase = token0 & (Tt - 1);
        g_dists[((size_t)bh * NCc + c) * Tt + tbase + tt] = sdl[c][tt];
    }
    if (threadIdx.x == 0) g_aux_part[blockIdx.x] = saux;
}

// ---------------- kernel 2: radix-select top-WSZ per (b,h,c) ----------------
__device__ __forceinline__ unsigned warp_incl_scan(unsigned v, int lane) {
#pragma unroll
    for (int off = 1; off < 32; off <<= 1) {
        unsigned t = __shfl_up_sync(0xffffffffu, v, off);
        if (lane >= off) v += t;
    }
    return v;
}

__device__ __forceinline__ void find_bin(unsigned* h, unsigned* wsum,
                                         unsigned* s_bin, unsigned* s_k, int tid) {
    int lane = tid & 31, w = tid >> 5;
    unsigned K = *s_k;
    unsigned tot = 0;
#pragma unroll
    for (int r = 0; r < 16; r++) tot += h[tid * 16 + r];
    unsigned p = warp_incl_scan(tot, lane);
    if (lane == 31) wsum[w] = p;
    __syncthreads();
    unsigned off = 0, S = 0;
#pragma unroll
    for (int i = 0; i < 8; i++) {
        unsigned x = wsum[i];
        S += x;
        if (i < w) off += x;
    }
    unsigned above = S - (p + off);
    unsigned run = above;
#pragma unroll
    for (int r = 15; r >= 0; r--) {
        unsigned cc = h[tid * 16 + r];
        run += cc;
        if (run >= K && run - cc < K) {
            *s_bin = (unsigned)(tid * 16 + r);
            *s_k = K - (run - cc);
        }
    }
    __syncthreads();
}

__global__ void __launch_bounds__(256) topk_kernel() {
    __shared__ unsigned su[Tt];
    __shared__ unsigned h[4096];
    __shared__ unsigned wsum[8];
    __shared__ unsigned s_bin, s_k;
    int tid = threadIdx.x;
    int lane = tid & 31, w = tid >> 5;
    int bhc = blockIdx.x;
    const float* dc = g_dists + (size_t)bhc * Tt;

    for (int i = tid; i < Tt; i += 256) {
        unsigned uu = __float_as_uint(dc[i]);
        uu = (uu & 0x80000000u) ? ~uu : (uu | 0x80000000u);
        su[i] = uu;
        h[i] = 0u;
    }
    if (tid == 0) s_k = WSZc;
    __syncthreads();

    for (int i = tid; i < Tt; i += 256) atomicAdd(&h[su[i] >> 20], 1u);
    __syncthreads();
    find_bin(h, wsum, &s_bin, &s_k, tid);
    unsigned b1 = s_bin;
    for (int i = tid; i < 4096; i += 256) h[i] = 0u;
    __syncthreads();

    for (int i = tid; i < Tt; i += 256)
        if ((su[i] >> 20) == b1) atomicAdd(&h[(su[i] >> 8) & 0xFFFu], 1u);
    __syncthreads();
    find_bin(h, wsum, &s_bin, &s_k, tid);
    unsigned b2 = s_bin;
    for (int i = tid; i < 4096; i += 256) h[i] = 0u;
    __syncthreads();

    unsigned hi20 = (b1 << 12) | b2;
    for (int i = tid; i < Tt; i += 256)
        if ((su[i] >> 8) == hi20) atomicAdd(&h[su[i] & 0xFFu], 1u);
    __syncthreads();
    find_bin(h, wsum, &s_bin, &s_k, tid);
    unsigned b3 = s_bin;
    unsigned m = s_k;
    unsigned thr = (b1 << 20) | (b2 << 8) | b3;

    unsigned gt = 0, eq = 0;
    int base = tid * 16;
#pragma unroll
    for (int r = 0; r < 16; r++) {
        unsigned uu = su[base + r];
        gt += (uu > thr);
        eq += (uu == thr);
    }
    unsigned mypack = (gt << 16) | eq;
    unsigned p = warp_incl_scan(mypack, lane);
    if (lane == 31) wsum[w] = p;
    __syncthreads();
    unsigned off = 0;
#pragma unroll
    for (int i = 0; i < 8; i++)
        if (i < w) off += wsum[i];
    unsigned excl = p + off - mypack;
    unsigned gtb = excl >> 16, eqb = excl & 0xFFFFu;
    int bh = bhc >> 4;
#pragma unroll
    for (int r = 0; r < 16; r++) {
        unsigned uu = su[base + r];
        if (uu > thr) {
            unsigned emin = eqb < m ? eqb : m;
            int pos = (int)(gtb + emin);
            g_idx[(size_t)bhc * WSZc + pos] = base + r;
            atomicAdd(&g_cnt[bh * Tt + base + r], 1);
            gtb++;
        } else if (uu == thr) {
            if (eqb < m) {
                int pos = (int)(gtb + eqb);
                g_idx[(size_t)bhc * WSZc + pos] = base + r;
                atomicAdd(&g_cnt[bh * Tt + base + r], 1);
            }
            eqb++;
        }
    }
}

// ---------------- kernel 3: tf32 tensor-core windowed attention ----------------
// Fused GEMM1->shuffle->GEMM2 per k-step: P never touches smem.
// Double-buffered K/V staging with LDG prefetch overlapped with mma compute.
__device__ __forceinline__ unsigned f2tf(float f) {
    unsigned u;
    asm("cvt.rna.tf32.f32 %0, %1;" : "=r"(u) : "f"(f));
    return u;
}
__device__ __forceinline__ void mma8(float* d, const unsigned* a, uint2 b) {
    asm volatile("mma.sync.aligned.m16n8k8.row.col.f32.tf32.tf32.f32 "
                 "{%0,%1,%2,%3}, {%4,%5,%6,%7}, {%8,%9}, {%0,%1,%2,%3};"
                 : "+f"(d[0]), "+f"(d[1]), "+f"(d[2]), "+f"(d[3])
                 : "r"(a[0]), "r"(a[1]), "r"(a[2]), "r"(a[3]), "r"(b.x), "r"(b.y));
}

// accumulator-layout (16x8 tile) -> A-operand layout via intra-quad shuffles.
// input s = {P[g][2c], P[g][2c+1], P[g+8][2c], P[g+8][2c+1]} (post exp/mask)
// output A = tf32{P[g][c], P[g+8][c], P[g][c+4], P[g+8][c+4]}
__device__ __forceinline__ void shuffle_p(const float* s, unsigned* A, int c) {
    int hq = c >> 1, e = c & 1;
    float v00 = __shfl_sync(0xffffffffu, s[0], hq, 4);
    float v01 = __shfl_sync(0xffffffffu, s[1], hq, 4);
    float v10 = __shfl_sync(0xffffffffu, s[2], hq, 4);
    float v11 = __shfl_sync(0xffffffffu, s[3], hq, 4);
    float v20 = __shfl_sync(0xffffffffu, s[0], hq + 2, 4);
    float v21 = __shfl_sync(0xffffffffu, s[1], hq + 2, 4);
    float v30 = __shfl_sync(0xffffffffu, s[2], hq + 2, 4);
    float v31 = __shfl_sync(0xffffffffu, s[3], hq + 2, 4);
    A[0] = f2tf(e ? v01 : v00);
    A[1] = f2tf(e ? v11 : v10);
    A[2] = f2tf(e ? v21 : v20);
    A[3] = f2tf(e ? v31 : v30);
}

// mask + exp + rowsum, in place
__device__ __forceinline__ void epi_vals(int t, int jc, int nt, int g, int c,
                                         float* s, float& l0, float& l1) {
    int i0 = 16 * t + g, i1 = i0 + 8;
    int j0 = 64 * jc + 8 * nt + 2 * c, j1 = j0 + 1;
    s[0] = (j0 > i0) ? 0.f : (j0 == i0) ? ((i0 == 0) ? 1.f : 0.f) : __expf(s[0] * 0.125f);
    s[1] = (j1 > i0) ? 0.f : (j1 == i0) ? 0.f : __expf(s[1] * 0.125f);
    s[2] = (j0 > i1) ? 0.f : (j0 == i1) ? 0.f : __expf(s[2] * 0.125f);
    s[3] = (j1 > i1) ? 0.f : (j1 == i1) ? 0.f : __expf(s[3] * 0.125f);
    l0 += s[0] + s[1];
    l1 += s[2] + s[3];
}

#define KV_BUF 4096                    // u32 per K (or V) buffer
#define ATTN_SMEM_BYTES (4 * KV_BUF * 4)   // KF[2] + VF[2] = 64KB

__global__ void __launch_bounds__(256, 1) attn_kernel(const float* __restrict__ q,
                                                      const float* __restrict__ v,
                                                      float* __restrict__ out) {
    extern __shared__ unsigned smu[];  // [KF0, KF1, VF0, VF1]
    __shared__ int sidx[WSZc];

    int tid = threadIdx.x;
    int bhc = blockIdx.x;
    int bh = bhc >> 4;
    int w = tid >> 5, lane = tid & 31;
    int g = lane >> 2, c = lane & 3;
    int t0 = w, t1 = 15 - w;   // t1 > t0 always

    sidx[tid] = g_idx[(size_t)bhc * WSZc + tid];
    __syncthreads();

    // ---- Q A-fragments into registers ----
    unsigned A0[8][4], A1[8][4];
    {
        const float* qb = q + (size_t)bh * Tt * Dd;
        const float* r00 = qb + (size_t)sidx[16 * t0 + g] * Dd;
        const float* r01 = qb + (size_t)sidx[16 * t0 + g + 8] * Dd;
        const float* r10 = qb + (size_t)sidx[16 * t1 + g] * Dd;
        const float* r11 = qb + (size_t)sidx[16 * t1 + g + 8] * Dd;
#pragma unroll
        for (int ks = 0; ks < 8; ks++) {
            A0[ks][0] = f2tf(r00[8 * ks + c]);
            A0[ks][1] = f2tf(r01[8 * ks + c]);
            A0[ks][2] = f2tf(r00[8 * ks + c + 4]);
            A0[ks][3] = f2tf(r01[8 * ks + c + 4]);
            A1[ks][0] = f2tf(r10[8 * ks + c]);
            A1[ks][1] = f2tf(r11[8 * ks + c]);
            A1[ks][2] = f2tf(r10[8 * ks + c + 4]);
            A1[ks][3] = f2tf(r11[8 * ks + c + 4]);
        }
    }

    float O0[8][4], O1[8][4];
#pragma unroll
    for (int nt = 0; nt < 8; nt++)
#pragma unroll
        for (int r = 0; r < 4; r++) { O0[nt][r] = 0.f; O1[nt][r] = 0.f; }
    float lp0[2] = {0.f, 0.f}, lp1[2] = {0.f, 0.f};

    // staging identities
    int r = tid >> 2, part = tid & 3;
    int gk = r & 7, ntk = r >> 3;                       // K-frag roles
    int ks2v = r >> 3, c0v = r & 3, halfv = (r >> 2) & 1;  // V-frag roles
    float4 kreg[4], vreg[4];

    // prologue: load + store chunk 0
    {
        int gj = sidx[r];
        const float4* xs = (const float4*)(g_x + ((size_t)bh * Tt + gj) * Dd) + part * 4;
        const float4* vs = (const float4*)(v + ((size_t)bh * Tt + gj) * Dd) + part * 4;
#pragma unroll
        for (int e4 = 0; e4 < 4; e4++) { kreg[e4] = xs[e4]; vreg[e4] = vs[e4]; }
    }
#pragma unroll
    for (int e4 = 0; e4 < 4; e4++) {
        int d0 = part * 16 + e4 * 4;
        {
            int ks = d0 >> 3, half = (d0 >> 2) & 1;
            unsigned base = (unsigned)(((ks * 8 + ntk) * 32 + gk * 4) * 2 + half);
            smu[base + 0] = f2tf(kreg[e4].x);
            smu[base + 2] = f2tf(kreg[e4].y);
            smu[base + 4] = f2tf(kreg[e4].z);
            smu[base + 6] = f2tf(kreg[e4].w);
        }
        {
            int nt2 = d0 >> 3;
            unsigned base = (unsigned)(2 * KV_BUF + ((ks2v * 8 + nt2) * 32 + (d0 & 7) * 4 + c0v) * 2 + halfv);
            smu[base + 0] = f2tf(vreg[e4].x);
            smu[base + 8] = f2tf(vreg[e4].y);
            smu[base + 16] = f2tf(vreg[e4].z);
            smu[base + 24] = f2tf(vreg[e4].w);
        }
    }
    __syncthreads();

    for (int jc = 0; jc < 4; jc++) {
        // prefetch next chunk (LDGs overlap with compute below)
        if (jc < 3) {
            int gj = sidx[(jc + 1) * 64 + r];
            const float4* xs = (const float4*)(g_x + ((size_t)bh * Tt + gj) * Dd) + part * 4;
            const float4* vs = (const float4*)(v + ((size_t)bh * Tt + gj) * Dd) + part * 4;
#pragma unroll
            for (int e4 = 0; e4 < 4; e4++) { kreg[e4] = xs[e4]; vreg[e4] = vs[e4]; }
        }

        const unsigned* KF = smu + (jc & 1) * KV_BUF;
        const unsigned* VF = smu + 2 * KV_BUF + (jc & 1) * KV_BUF;
        int lim0 = 2 * t0 + 1 - 8 * jc;
        int lim1 = 2 * t1 + 1 - 8 * jc;

#pragma unroll
        for (int nt = 0; nt < 8; nt++) {
            if (nt > lim1) break;
            bool need0 = (nt <= lim0);
            float s1v[4] = {0.f, 0.f, 0.f, 0.f};
            float s0v[4] = {0.f, 0.f, 0.f, 0.f};
#pragma unroll
            for (int ks = 0; ks < 8; ks++) {
                uint2 b = *(const uint2*)&KF[((ks * 8 + nt) * 32 + lane) * 2];
                mma8(s1v, A1[ks], b);
                if (need0) mma8(s0v, A0[ks], b);
            }
            epi_vals(t1, jc, nt, g, c, s1v, lp1[0], lp1[1]);
            unsigned P1[4], P0[4];
            shuffle_p(s1v, P1, c);
            if (need0) {
                epi_vals(t0, jc, nt, g, c, s0v, lp0[0], lp0[1]);
                shuffle_p(s0v, P0, c);
            }
#pragma unroll
            for (int nt2 = 0; nt2 < 8; nt2++) {
                uint2 bv = *(const uint2*)&VF[((nt * 8 + nt2) * 32 + lane) * 2];
                mma8(O1[nt2], P1, bv);
                if (need0) mma8(O0[nt2], P0, bv);
            }
        }

        // store prefetched chunk into the other buffer (read last at jc-1; safe)
        if (jc < 3) {
            unsigned* KFn = smu + ((jc + 1) & 1) * KV_BUF;
            unsigned* VFn = smu + 2 * KV_BUF + ((jc + 1) & 1) * KV_BUF;
#pragma unroll
            for (int e4 = 0; e4 < 4; e4++) {
                int d0 = part * 16 + e4 * 4;
                {
                    int ks = d0 >> 3, half = (d0 >> 2) & 1;
                    unsigned base = (unsigned)(((ks * 8 + ntk) * 32 + gk * 4) * 2 + half);
                    KFn[base + 0] = f2tf(kreg[e4].x);
                    KFn[base + 2] = f2tf(kreg[e4].y);
                    KFn[base + 4] = f2tf(kreg[e4].z);
                    KFn[base + 6] = f2tf(kreg[e4].w);
                }
                {
                    int nt2 = d0 >> 3;
                    unsigned base = (unsigned)(((ks2v * 8 + nt2) * 32 + (d0 & 7) * 4 + c0v) * 2 + halfv);
                    VFn[base + 0] = f2tf(vreg[e4].x);
                    VFn[base + 8] = f2tf(vreg[e4].y);
                    VFn[base + 16] = f2tf(vreg[e4].z);
                    VFn[base + 24] = f2tf(vreg[e4].w);
                }
            }
        }
        __syncthreads();
    }

    // ---- row-sum reduce across quad, normalize, scatter ----
    float rs0[2], rs1[2];
#pragma unroll
    for (int hf = 0; hf < 2; hf++) {
        float s = lp0[hf];
        s += __shfl_xor_sync(0xffffffffu, s, 1);
        s += __shfl_xor_sync(0xffffffffu, s, 2);
        rs0[hf] = 1.f / s;
        s = lp1[hf];
        s += __shfl_xor_sync(0xffffffffu, s, 1);
        s += __shfl_xor_sync(0xffffffffu, s, 2);
        rs1[hf] = 1.f / s;
    }
    {
        float* ob = out + (size_t)bh * Tt * Dd;
        float* o00 = ob + (size_t)sidx[16 * t0 + g] * Dd;
        float* o01 = ob + (size_t)sidx[16 * t0 + g + 8] * Dd;
        float* o10 = ob + (size_t)sidx[16 * t1 + g] * Dd;
        float* o11 = ob + (size_t)sidx[16 * t1 + g + 8] * Dd;
#pragma unroll
        for (int nt2 = 0; nt2 < 8; nt2++) {
            int col = 8 * nt2 + 2 * c;
            atomicAdd(o00 + col, O0[nt2][0] * rs0[0]);
            atomicAdd(o00 + col + 1, O0[nt2][1] * rs0[0]);
            atomicAdd(o01 + col, O0[nt2][2] * rs0[1]);
            atomicAdd(o01 + col + 1, O0[nt2][3] * rs0[1]);
            atomicAdd(o10 + col, O1[nt2][0] * rs1[0]);
            atomicAdd(o10 + col + 1, O1[nt2][1] * rs1[0]);
            atomicAdd(o11 + col, O1[nt2][2] * rs1[1]);
            atomicAdd(o11 + col + 1, O1[nt2][3] * rs1[1]);
        }
    }
}

// ---------------- kernel 4: divide by count + aux loss ----------------
__global__ void finalize_kernel(float* out, int out_size) {
    const int n = Bq * Hh * Tt * Dd;
    const int n4 = n / 4;
    int i = blockIdx.x * blockDim.x + threadIdx.x;
    int stride = gridDim.x * blockDim.x;
    for (int p = i; p < n4; p += stride) {
        float4 o = ((float4*)out)[p];
        float cc = (float)g_cnt[p >> 4];
        float inv = 1.f / (cc + 1e-5f);
        o.x *= inv; o.y *= inv; o.z *= inv; o.w *= inv;
        ((float4*)out)[p] = o;
    }
    if (blockIdx.x == 0) {
        __shared__ float sred[256];
        float s = 0.f;
        for (int p = threadIdx.x; p < Bq * Hh * Tt / 8; p += 256) s += g_aux_part[p];
        sred[threadIdx.x] = s;
        __syncthreads();
        for (int off = 128; off; off >>= 1) {
            if (threadIdx.x < off) sred[threadIdx.x] += sred[threadIdx.x + off];
            __syncthreads();
        }
        if (threadIdx.x == 0 && out_size > n)
            out[n] = sred[0] * (1e-4f / (float)n);
    }
}

// ---------------- launch ----------------
extern "C" void kernel_launch(void* const* d_in, const int* in_sizes, int n_in,
                              void* d_out, int out_size) {
    const float* q = (const float*)d_in[0];
    const float* k = (const float*)d_in[1];
    const float* v = (const float*)d_in[2];
    const float* means = (const float*)d_in[3];
    float* out = (float*)d_out;

    cudaFuncSetAttribute(attn_kernel, cudaFuncAttributeMaxDynamicSharedMemorySize,
                         ATTN_SMEM_BYTES);

    route_kernel<<<Bq * Hh * Tt / 8, 256>>>(k, means, out);
    topk_kernel<<<Bq * Hh * NCc, 256>>>();
    attn_kernel<<<Bq * Hh * NCc, 256, ATTN_SMEM_BYTES>>>(q, v, out);
    finalize_kernel<<<2048, 256>>>(out, out_size);
}

// round 8
// speedup vs baseline: 2.6421x; 1.0257x over previous
#include <cuda_runtime.h>
#include <math.h>

#define Bq 4
#define Hh 8
#define Tt 4096
#define Dd 64
#define NCc 16
#define WSZc 256

// ---------------- scratch (no allocations allowed) ----------------
__device__ float g_dists[Bq * Hh * NCc * Tt];     // [bh, c, t], 8MB
__device__ int   g_idx[Bq * Hh * NCc * WSZc];     // sorted top-k indices
__device__ int   g_cnt[Bq * Hh * Tt];             // scatter counts
__device__ float g_aux_part[Bq * Hh * Tt / 8];    // per-route-block aux partials

// ---------------- kernel 1: route (+ zero cnt) ----------------
__global__ void route_kernel(const float* __restrict__ k,
                             const float* __restrict__ means) {
    __shared__ float sm[NCc * Dd];
    __shared__ float saux;
    __shared__ float sdl[NCc][8];

    // zero g_cnt (must complete before topk's atomics)
    {
        long long gid = (long long)blockIdx.x * blockDim.x + threadIdx.x;
        const long long c4 = (long long)Bq * Hh * Tt / 4;
        if (gid < c4) ((int4*)g_cnt)[gid] = make_int4(0, 0, 0, 0);
    }

    int token0 = blockIdx.x * 8;
    int bh = token0 / Tt;
    int h = bh % Hh;
    const float* mh = means + (size_t)h * NCc * Dd;
    for (int i = threadIdx.x; i < NCc * Dd; i += blockDim.x) sm[i] = mh[i];
    if (threadIdx.x == 0) saux = 0.f;
    __syncthreads();

    int warp = threadIdx.x >> 5, lane = threadIdx.x & 31;
    int token = token0 + warp;
    int t = token & (Tt - 1);

    float2 kv = ((const float2*)(k + (size_t)token * Dd))[lane];
    float ss = kv.x * kv.x + kv.y * kv.y;
#pragma unroll
    for (int o = 16; o; o >>= 1) ss += __shfl_xor_sync(0xffffffffu, ss, o);
    float inv = rsqrtf(ss);
    float2 xv = make_float2(kv.x * inv, kv.y * inv);

    float dl[NCc];
#pragma unroll
    for (int c = 0; c < NCc; c++)
        dl[c] = xv.x * sm[c * Dd + 2 * lane] + xv.y * sm[c * Dd + 2 * lane + 1];
#pragma unroll
    for (int o = 16; o; o >>= 1) {
#pragma unroll
        for (int c = 0; c < NCc; c++)
            dl[c] += __shfl_xor_sync(0xffffffffu, dl[c], o);
    }
    int bestc = 0;
    float bestv = dl[0];
#pragma unroll
    for (int c = 1; c < NCc; c++)
        if (dl[c] > bestv) { bestv = dl[c]; bestc = c; }

    if (lane == 0) {
#pragma unroll
        for (int c = 0; c < NCc; c++) sdl[c][warp] = dl[c];
    }

    float mx = sm[bestc * Dd + 2 * lane];
    float my = sm[bestc * Dd + 2 * lane + 1];
    float ex = xv.x - mx, ey = xv.y - my;
    float e = ex * ex + ey * ey;
#pragma unroll
    for (int o = 16; o; o >>= 1) e += __shfl_xor_sync(0xffffffffu, e, o);
    if (lane == 0) atomicAdd(&saux, e);
    __syncthreads();

    if (threadIdx.x < 128) {
        int c = threadIdx.x >> 3, tt = threadIdx.x & 7;
        int tbase = token0 & (Tt - 1);
        g_dists[((size_t)bh * NCc + c) * Tt + tbase + tt] = sdl[c][tt];
    }
    if (threadIdx.x == 0) g_aux_part[blockIdx.x] = saux;
}

// ---------------- kernel 2: radix-select top-WSZ per (b,h,c) (+ zero out) ----
__device__ __forceinline__ unsigned warp_incl_scan(unsigned v, int lane) {
#pragma unroll
    for (int off = 1; off < 32; off <<= 1) {
        unsigned t = __shfl_up_sync(0xffffffffu, v, off);
        if (lane >= off) v += t;
    }
    return v;
}

__device__ __forceinline__ void find_bin(unsigned* h, unsigned* wsum,
                                         unsigned* s_bin, unsigned* s_k, int tid) {
    int lane = tid & 31, w = tid >> 5;
    unsigned K = *s_k;
    unsigned tot = 0;
#pragma unroll
    for (int r = 0; r < 16; r++) tot += h[tid * 16 + r];
    unsigned p = warp_incl_scan(tot, lane);
    if (lane == 31) wsum[w] = p;
    __syncthreads();
    unsigned off = 0, S = 0;
#pragma unroll
    for (int i = 0; i < 8; i++) {
        unsigned x = wsum[i];
        S += x;
        if (i < w) off += x;
    }
    unsigned above = S - (p + off);
    unsigned run = above;
#pragma unroll
    for (int r = 15; r >= 0; r--) {
        unsigned cc = h[tid * 16 + r];
        run += cc;
        if (run >= K && run - cc < K) {
            *s_bin = (unsigned)(tid * 16 + r);
            *s_k = K - (run - cc);
        }
    }
    __syncthreads();
}

__global__ void __launch_bounds__(256) topk_kernel(float* __restrict__ out) {
    __shared__ unsigned su[Tt];
    __shared__ unsigned h[4096];
    __shared__ unsigned wsum[8];
    __shared__ unsigned s_bin, s_k;
    int tid = threadIdx.x;
    int lane = tid & 31, w = tid >> 5;
    int bhc = blockIdx.x;
    const float* dc = g_dists + (size_t)bhc * Tt;

    // zero this block's slice of out (DRAM slots are idle in this kernel)
    {
        float4* o4 = (float4*)out + (size_t)blockIdx.x * 4096;
        for (int i = tid; i < 4096; i += 256)
            o4[i] = make_float4(0.f, 0.f, 0.f, 0.f);
    }

    for (int i = tid; i < Tt; i += 256) {
        unsigned uu = __float_as_uint(dc[i]);
        uu = (uu & 0x80000000u) ? ~uu : (uu | 0x80000000u);
        su[i] = uu;
        h[i] = 0u;
    }
    if (tid == 0) s_k = WSZc;
    __syncthreads();

    for (int i = tid; i < Tt; i += 256) atomicAdd(&h[su[i] >> 20], 1u);
    __syncthreads();
    find_bin(h, wsum, &s_bin, &s_k, tid);
    unsigned b1 = s_bin;
    for (int i = tid; i < 4096; i += 256) h[i] = 0u;
    __syncthreads();

    for (int i = tid; i < Tt; i += 256)
        if ((su[i] >> 20) == b1) atomicAdd(&h[(su[i] >> 8) & 0xFFFu], 1u);
    __syncthreads();
    find_bin(h, wsum, &s_bin, &s_k, tid);
    unsigned b2 = s_bin;
    for (int i = tid; i < 4096; i += 256) h[i] = 0u;
    __syncthreads();

    unsigned hi20 = (b1 << 12) | b2;
    for (int i = tid; i < Tt; i += 256)
        if ((su[i] >> 8) == hi20) atomicAdd(&h[su[i] & 0xFFu], 1u);
    __syncthreads();
    find_bin(h, wsum, &s_bin, &s_k, tid);
    unsigned b3 = s_bin;
    unsigned m = s_k;
    unsigned thr = (b1 << 20) | (b2 << 8) | b3;

    unsigned gt = 0, eq = 0;
    int base = tid * 16;
#pragma unroll
    for (int r = 0; r < 16; r++) {
        unsigned uu = su[base + r];
        gt += (uu > thr);
        eq += (uu == thr);
    }
    unsigned mypack = (gt << 16) | eq;
    unsigned p = warp_incl_scan(mypack, lane);
    if (lane == 31) wsum[w] = p;
    __syncthreads();
    unsigned off = 0;
#pragma unroll
    for (int i = 0; i < 8; i++)
        if (i < w) off += wsum[i];
    unsigned excl = p + off - mypack;
    unsigned gtb = excl >> 16, eqb = excl & 0xFFFFu;
    int bh = bhc >> 4;
#pragma unroll
    for (int r = 0; r < 16; r++) {
        unsigned uu = su[base + r];
        if (uu > thr) {
            unsigned emin = eqb < m ? eqb : m;
            int pos = (int)(gtb + emin);
            g_idx[(size_t)bhc * WSZc + pos] = base + r;
            atomicAdd(&g_cnt[bh * Tt + base + r], 1);
            gtb++;
        } else if (uu == thr) {
            if (eqb < m) {
                int pos = (int)(gtb + eqb);
                g_idx[(size_t)bhc * WSZc + pos] = base + r;
                atomicAdd(&g_cnt[bh * Tt + base + r], 1);
            }
            eqb++;
        }
    }
}

// ---------------- kernel 3: tf32 tensor-core windowed attention ----------------
// All 4 K/V chunks staged upfront (128KB smem) -> ONE barrier, then barrier-free
// compute. K normalized on the fly (g_x eliminated). Fused GEMM1->shuffle->GEMM2.
__device__ __forceinline__ unsigned f2tf(float f) {
    unsigned u;
    asm("cvt.rna.tf32.f32 %0, %1;" : "=r"(u) : "f"(f));
    return u;
}
__device__ __forceinline__ void mma8(float* d, const unsigned* a, uint2 b) {
    asm volatile("mma.sync.aligned.m16n8k8.row.col.f32.tf32.tf32.f32 "
                 "{%0,%1,%2,%3}, {%4,%5,%6,%7}, {%8,%9}, {%0,%1,%2,%3};"
                 : "+f"(d[0]), "+f"(d[1]), "+f"(d[2]), "+f"(d[3])
                 : "r"(a[0]), "r"(a[1]), "r"(a[2]), "r"(a[3]), "r"(b.x), "r"(b.y));
}

// accumulator-layout (16x8) -> A-operand layout via intra-quad shuffles
__device__ __forceinline__ void shuffle_p(const float* s, unsigned* A, int c) {
    int hq = c >> 1, e = c & 1;
    float v00 = __shfl_sync(0xffffffffu, s[0], hq, 4);
    float v01 = __shfl_sync(0xffffffffu, s[1], hq, 4);
    float v10 = __shfl_sync(0xffffffffu, s[2], hq, 4);
    float v11 = __shfl_sync(0xffffffffu, s[3], hq, 4);
    float v20 = __shfl_sync(0xffffffffu, s[0], hq + 2, 4);
    float v21 = __shfl_sync(0xffffffffu, s[1], hq + 2, 4);
    float v30 = __shfl_sync(0xffffffffu, s[2], hq + 2, 4);
    float v31 = __shfl_sync(0xffffffffu, s[3], hq + 2, 4);
    A[0] = f2tf(e ? v01 : v00);
    A[1] = f2tf(e ? v11 : v10);
    A[2] = f2tf(e ? v21 : v20);
    A[3] = f2tf(e ? v31 : v30);
}

__device__ __forceinline__ void epi_vals(int t, int jc, int nt, int g, int c,
                                         float* s, float& l0, float& l1) {
    int i0 = 16 * t + g, i1 = i0 + 8;
    int j0 = 64 * jc + 8 * nt + 2 * c, j1 = j0 + 1;
    s[0] = (j0 > i0) ? 0.f : (j0 == i0) ? ((i0 == 0) ? 1.f : 0.f) : __expf(s[0] * 0.125f);
    s[1] = (j1 > i0) ? 0.f : (j1 == i0) ? 0.f : __expf(s[1] * 0.125f);
    s[2] = (j0 > i1) ? 0.f : (j0 == i1) ? 0.f : __expf(s[2] * 0.125f);
    s[3] = (j1 > i1) ? 0.f : (j1 == i1) ? 0.f : __expf(s[3] * 0.125f);
    l0 += s[0] + s[1];
    l1 += s[2] + s[3];
}

#define KV_BUF 4096                        // u32 per chunk per operand
#define ATTN_SMEM_BYTES (8 * KV_BUF * 4)   // KF[4] + VF[4] = 128KB

__global__ void __launch_bounds__(256, 1) attn_kernel(const float* __restrict__ q,
                                                      const float* __restrict__ k,
                                                      const float* __restrict__ v,
                                                      float* __restrict__ out) {
    extern __shared__ unsigned smu[];  // [KF0..KF3, VF0..VF3]
    __shared__ int sidx[WSZc];

    int tid = threadIdx.x;
    int bhc = blockIdx.x;
    int bh = bhc >> 4;
    int w = tid >> 5, lane = tid & 31;
    int g = lane >> 2, c = lane & 3;
    int t0 = w, t1 = 15 - w;   // t1 > t0 always

    sidx[tid] = g_idx[(size_t)bhc * WSZc + tid];
    __syncthreads();

    // ---- stage ALL K/V: thread tid owns key row tid (chunk tid>>6, row tid&63)
    {
        int gj = sidx[tid];
        int jcc = tid >> 6, r = tid & 63;
        const float4* ks = (const float4*)(k + ((size_t)bh * Tt + gj) * Dd);
        const float4* vs = (const float4*)(v + ((size_t)bh * Tt + gj) * Dd);
        unsigned* KF = smu + jcc * KV_BUF;
        unsigned* VF = smu + 4 * KV_BUF + jcc * KV_BUF;
        int gk = r & 7, ntk = r >> 3;
        int ks2v = r >> 3, c0v = r & 3, halfv = (r >> 2) & 1;

        float4 kv[16];
        float ss = 0.f;
#pragma unroll
        for (int e = 0; e < 16; e++) {
            kv[e] = ks[e];
            ss += kv[e].x * kv[e].x + kv[e].y * kv[e].y +
                  kv[e].z * kv[e].z + kv[e].w * kv[e].w;
        }
        float inv = rsqrtf(ss);
#pragma unroll
        for (int e = 0; e < 16; e++) {
            int d0 = e * 4;
            int kss = d0 >> 3, half = (d0 >> 2) & 1;
            unsigned base = (unsigned)(((kss * 8 + ntk) * 32 + gk * 4) * 2 + half);
            KF[base + 0] = f2tf(kv[e].x * inv);
            KF[base + 2] = f2tf(kv[e].y * inv);
            KF[base + 4] = f2tf(kv[e].z * inv);
            KF[base + 6] = f2tf(kv[e].w * inv);
        }
#pragma unroll
        for (int e = 0; e < 16; e++) {
            float4 vv = vs[e];
            int d0 = e * 4, nt2 = d0 >> 3;
            unsigned base = (unsigned)(((ks2v * 8 + nt2) * 32 + (d0 & 7) * 4 + c0v) * 2 + halfv);
            VF[base + 0] = f2tf(vv.x);
            VF[base + 8] = f2tf(vv.y);
            VF[base + 16] = f2tf(vv.z);
            VF[base + 24] = f2tf(vv.w);
        }
    }

    // ---- Q A-fragments into registers ----
    unsigned A0[8][4], A1[8][4];
    {
        const float* qb = q + (size_t)bh * Tt * Dd;
        const float* r00 = qb + (size_t)sidx[16 * t0 + g] * Dd;
        const float* r01 = qb + (size_t)sidx[16 * t0 + g + 8] * Dd;
        const float* r10 = qb + (size_t)sidx[16 * t1 + g] * Dd;
        const float* r11 = qb + (size_t)sidx[16 * t1 + g + 8] * Dd;
#pragma unroll
        for (int ks = 0; ks < 8; ks++) {
            A0[ks][0] = f2tf(r00[8 * ks + c]);
            A0[ks][1] = f2tf(r01[8 * ks + c]);
            A0[ks][2] = f2tf(r00[8 * ks + c + 4]);
            A0[ks][3] = f2tf(r01[8 * ks + c + 4]);
            A1[ks][0] = f2tf(r10[8 * ks + c]);
            A1[ks][1] = f2tf(r11[8 * ks + c]);
            A1[ks][2] = f2tf(r10[8 * ks + c + 4]);
            A1[ks][3] = f2tf(r11[8 * ks + c + 4]);
        }
    }

    float O0[8][4], O1[8][4];
#pragma unroll
    for (int nt = 0; nt < 8; nt++)
#pragma unroll
        for (int r = 0; r < 4; r++) { O0[nt][r] = 0.f; O1[nt][r] = 0.f; }
    float lp0[2] = {0.f, 0.f}, lp1[2] = {0.f, 0.f};

    __syncthreads();   // the ONLY mainloop barrier

    for (int jc = 0; jc < 4; jc++) {
        int lim1 = 2 * t1 + 1 - 8 * jc;
        if (lim1 < 0) break;
        int lim0 = 2 * t0 + 1 - 8 * jc;
        const unsigned* KF = smu + jc * KV_BUF;
        const unsigned* VF = smu + 4 * KV_BUF + jc * KV_BUF;

#pragma unroll
        for (int nt = 0; nt < 8; nt++) {
            if (nt > lim1) break;
            bool need0 = (nt <= lim0);
            float s1v[4] = {0.f, 0.f, 0.f, 0.f};
            float s0v[4] = {0.f, 0.f, 0.f, 0.f};
#pragma unroll
            for (int ks = 0; ks < 8; ks++) {
                uint2 b = *(const uint2*)&KF[((ks * 8 + nt) * 32 + lane) * 2];
                mma8(s1v, A1[ks], b);
                if (need0) mma8(s0v, A0[ks], b);
            }
            epi_vals(t1, jc, nt, g, c, s1v, lp1[0], lp1[1]);
            unsigned P1[4], P0[4];
            shuffle_p(s1v, P1, c);
            if (need0) {
                epi_vals(t0, jc, nt, g, c, s0v, lp0[0], lp0[1]);
                shuffle_p(s0v, P0, c);
            }
#pragma unroll
            for (int nt2 = 0; nt2 < 8; nt2++) {
                uint2 bv = *(const uint2*)&VF[((nt * 8 + nt2) * 32 + lane) * 2];
                mma8(O1[nt2], P1, bv);
                if (need0) mma8(O0[nt2], P0, bv);
            }
        }
    }

    // ---- row-sum reduce across quad, normalize, scatter ----
    float rs0[2], rs1[2];
#pragma unroll
    for (int hf = 0; hf < 2; hf++) {
        float s = lp0[hf];
        s += __shfl_xor_sync(0xffffffffu, s, 1);
        s += __shfl_xor_sync(0xffffffffu, s, 2);
        rs0[hf] = 1.f / s;
        s = lp1[hf];
        s += __shfl_xor_sync(0xffffffffu, s, 1);
        s += __shfl_xor_sync(0xffffffffu, s, 2);
        rs1[hf] = 1.f / s;
    }
    {
        float* ob = out + (size_t)bh * Tt * Dd;
        float* o00 = ob + (size_t)sidx[16 * t0 + g] * Dd;
        float* o01 = ob + (size_t)sidx[16 * t0 + g + 8] * Dd;
        float* o10 = ob + (size_t)sidx[16 * t1 + g] * Dd;
        float* o11 = ob + (size_t)sidx[16 * t1 + g + 8] * Dd;
#pragma unroll
        for (int nt2 = 0; nt2 < 8; nt2++) {
            int col = 8 * nt2 + 2 * c;
            atomicAdd(o00 + col, O0[nt2][0] * rs0[0]);
            atomicAdd(o00 + col + 1, O0[nt2][1] * rs0[0]);
            atomicAdd(o01 + col, O0[nt2][2] * rs0[1]);
            atomicAdd(o01 + col + 1, O0[nt2][3] * rs0[1]);
            atomicAdd(o10 + col, O1[nt2][0] * rs1[0]);
            atomicAdd(o10 + col + 1, O1[nt2][1] * rs1[0]);
            atomicAdd(o11 + col, O1[nt2][2] * rs1[1]);
            atomicAdd(o11 + col + 1, O1[nt2][3] * rs1[1]);
        }
    }
}

// ---------------- kernel 4: divide by count + aux loss ----------------
__global__ void finalize_kernel(float* out, int out_size) {
    const int n = Bq * Hh * Tt * Dd;
    const int n4 = n / 4;
    int i = blockIdx.x * blockDim.x + threadIdx.x;
    int stride = gridDim.x * blockDim.x;
    for (int p = i; p < n4; p += stride) {
        float4 o = ((float4*)out)[p];
        float cc = (float)g_cnt[p >> 4];
        float inv = 1.f / (cc + 1e-5f);
        o.x *= inv; o.y *= inv; o.z *= inv; o.w *= inv;
        ((float4*)out)[p] = o;
    }
    if (blockIdx.x == 0) {
        __shared__ float sred[256];
        float s = 0.f;
        for (int p = threadIdx.x; p < Bq * Hh * Tt / 8; p += 256) s += g_aux_part[p];
        sred[threadIdx.x] = s;
        __syncthreads();
        for (int off = 128; off; off >>= 1) {
            if (threadIdx.x < off) sred[threadIdx.x] += sred[threadIdx.x + off];
            __syncthreads();
        }
        if (threadIdx.x == 0 && out_size > n)
            out[n] = sred[0] * (1e-4f / (float)n);
    }
}

// ---------------- launch ----------------
extern "C" void kernel_launch(void* const* d_in, const int* in_sizes, int n_in,
                              void* d_out, int out_size) {
    const float* q = (const float*)d_in[0];
    const float* k = (const float*)d_in[1];
    const float* v = (const float*)d_in[2];
    const float* means = (const float*)d_in[3];
    float* out = (float*)d_out;

    cudaFuncSetAttribute(attn_kernel, cudaFuncAttributeMaxDynamicSharedMemorySize,
                         ATTN_SMEM_BYTES);

    route_kernel<<<Bq * Hh * Tt / 8, 256>>>(k, means);
    topk_kernel<<<Bq * Hh * NCc, 256>>>(out);
    attn_kernel<<<Bq * Hh * NCc, 256, ATTN_SMEM_BYTES>>>(q, k, v, out);
    finalize_kernel<<<2048, 256>>>(out, out_size);
}

// round 9
// speedup vs baseline: 2.7477x; 1.0399x over previous
#include <cuda_runtime.h>
#include <math.h>

#define Bq 4
#define Hh 8
#define Tt 4096
#define Dd 64
#define NCc 16
#define WSZc 256

// ---------------- scratch (no allocations allowed) ----------------
__device__ float g_dists[Bq * Hh * NCc * Tt];     // [bh, c, t], 8MB
__device__ int   g_idx[Bq * Hh * NCc * WSZc];     // sorted top-k indices
__device__ int   g_cnt[Bq * Hh * Tt];             // scatter counts
__device__ float g_aux_part[Bq * Hh * Tt / 8];    // per-route-block aux partials

// ---------------- kernel 1: route (+ zero cnt) ----------------
__global__ void route_kernel(const float* __restrict__ k,
                             const float* __restrict__ means) {
    __shared__ float sm[NCc * Dd];
    __shared__ float saux;
    __shared__ float sdl[NCc][8];

    {
        long long gid = (long long)blockIdx.x * blockDim.x + threadIdx.x;
        const long long c4 = (long long)Bq * Hh * Tt / 4;
        if (gid < c4) ((int4*)g_cnt)[gid] = make_int4(0, 0, 0, 0);
    }

    int token0 = blockIdx.x * 8;
    int bh = token0 / Tt;
    int h = bh % Hh;
    const float* mh = means + (size_t)h * NCc * Dd;
    for (int i = threadIdx.x; i < NCc * Dd; i += blockDim.x) sm[i] = mh[i];
    if (threadIdx.x == 0) saux = 0.f;
    __syncthreads();

    int warp = threadIdx.x >> 5, lane = threadIdx.x & 31;
    int token = token0 + warp;
    int t = token & (Tt - 1);

    float2 kv = ((const float2*)(k + (size_t)token * Dd))[lane];
    float ss = kv.x * kv.x + kv.y * kv.y;
#pragma unroll
    for (int o = 16; o; o >>= 1) ss += __shfl_xor_sync(0xffffffffu, ss, o);
    float inv = rsqrtf(ss);
    float2 xv = make_float2(kv.x * inv, kv.y * inv);

    float dl[NCc];
#pragma unroll
    for (int c = 0; c < NCc; c++)
        dl[c] = xv.x * sm[c * Dd + 2 * lane] + xv.y * sm[c * Dd + 2 * lane + 1];
#pragma unroll
    for (int o = 16; o; o >>= 1) {
#pragma unroll
        for (int c = 0; c < NCc; c++)
            dl[c] += __shfl_xor_sync(0xffffffffu, dl[c], o);
    }
    int bestc = 0;
    float bestv = dl[0];
#pragma unroll
    for (int c = 1; c < NCc; c++)
        if (dl[c] > bestv) { bestv = dl[c]; bestc = c; }

    if (lane == 0) {
#pragma unroll
        for (int c = 0; c < NCc; c++) sdl[c][warp] = dl[c];
    }

    float mx = sm[bestc * Dd + 2 * lane];
    float my = sm[bestc * Dd + 2 * lane + 1];
    float ex = xv.x - mx, ey = xv.y - my;
    float e = ex * ex + ey * ey;
#pragma unroll
    for (int o = 16; o; o >>= 1) e += __shfl_xor_sync(0xffffffffu, e, o);
    if (lane == 0) atomicAdd(&saux, e);
    __syncthreads();

    if (threadIdx.x < 128) {
        int c = threadIdx.x >> 3, tt = threadIdx.x & 7;
        int tbase = token0 & (Tt - 1);
        g_dists[((size_t)bh * NCc + c) * Tt + tbase + tt] = sdl[c][tt];
    }
    if (threadIdx.x == 0) g_aux_part[blockIdx.x] = saux;
}

// ---------------- kernel 2: radix-select top-WSZ per (b,h,c) (+ zero out) ----
__device__ __forceinline__ unsigned warp_incl_scan(unsigned v, int lane) {
#pragma unroll
    for (int off = 1; off < 32; off <<= 1) {
        unsigned t = __shfl_up_sync(0xffffffffu, v, off);
        if (lane >= off) v += t;
    }
    return v;
}

__device__ __forceinline__ void find_bin(unsigned* h, unsigned* wsum,
                                         unsigned* s_bin, unsigned* s_k, int tid) {
    int lane = tid & 31, w = tid >> 5;
    unsigned K = *s_k;
    unsigned tot = 0;
#pragma unroll
    for (int r = 0; r < 16; r++) tot += h[tid * 16 + r];
    unsigned p = warp_incl_scan(tot, lane);
    if (lane == 31) wsum[w] = p;
    __syncthreads();
    unsigned off = 0, S = 0;
#pragma unroll
    for (int i = 0; i < 8; i++) {
        unsigned x = wsum[i];
        S += x;
        if (i < w) off += x;
    }
    unsigned above = S - (p + off);
    unsigned run = above;
#pragma unroll
    for (int r = 15; r >= 0; r--) {
        unsigned cc = h[tid * 16 + r];
        run += cc;
        if (run >= K && run - cc < K) {
            *s_bin = (unsigned)(tid * 16 + r);
            *s_k = K - (run - cc);
        }
    }
    __syncthreads();
}

__global__ void __launch_bounds__(256) topk_kernel(float* __restrict__ out) {
    __shared__ unsigned su[Tt];
    __shared__ unsigned h[4096];
    __shared__ unsigned wsum[8];
    __shared__ unsigned s_bin, s_k;
    int tid = threadIdx.x;
    int lane = tid & 31, w = tid >> 5;
    int bhc = blockIdx.x;
    const float* dc = g_dists + (size_t)bhc * Tt;

    {
        float4* o4 = (float4*)out + (size_t)blockIdx.x * 4096;
        for (int i = tid; i < 4096; i += 256)
            o4[i] = make_float4(0.f, 0.f, 0.f, 0.f);
    }

    for (int i = tid; i < Tt; i += 256) {
        unsigned uu = __float_as_uint(dc[i]);
        uu = (uu & 0x80000000u) ? ~uu : (uu | 0x80000000u);
        su[i] = uu;
        h[i] = 0u;
    }
    if (tid == 0) s_k = WSZc;
    __syncthreads();

    for (int i = tid; i < Tt; i += 256) atomicAdd(&h[su[i] >> 20], 1u);
    __syncthreads();
    find_bin(h, wsum, &s_bin, &s_k, tid);
    unsigned b1 = s_bin;
    for (int i = tid; i < 4096; i += 256) h[i] = 0u;
    __syncthreads();

    for (int i = tid; i < Tt; i += 256)
        if ((su[i] >> 20) == b1) atomicAdd(&h[(su[i] >> 8) & 0xFFFu], 1u);
    __syncthreads();
    find_bin(h, wsum, &s_bin, &s_k, tid);
    unsigned b2 = s_bin;
    for (int i = tid; i < 4096; i += 256) h[i] = 0u;
    __syncthreads();

    unsigned hi20 = (b1 << 12) | b2;
    for (int i = tid; i < Tt; i += 256)
        if ((su[i] >> 8) == hi20) atomicAdd(&h[su[i] & 0xFFu], 1u);
    __syncthreads();
    find_bin(h, wsum, &s_bin, &s_k, tid);
    unsigned b3 = s_bin;
    unsigned m = s_k;
    unsigned thr = (b1 << 20) | (b2 << 8) | b3;

    unsigned gt = 0, eq = 0;
    int base = tid * 16;
#pragma unroll
    for (int r = 0; r < 16; r++) {
        unsigned uu = su[base + r];
        gt += (uu > thr);
        eq += (uu == thr);
    }
    unsigned mypack = (gt << 16) | eq;
    unsigned p = warp_incl_scan(mypack, lane);
    if (lane == 31) wsum[w] = p;
    __syncthreads();
    unsigned off = 0;
#pragma unroll
    for (int i = 0; i < 8; i++)
        if (i < w) off += wsum[i];
    unsigned excl = p + off - mypack;
    unsigned gtb = excl >> 16, eqb = excl & 0xFFFFu;
    int bh = bhc >> 4;
#pragma unroll
    for (int r = 0; r < 16; r++) {
        unsigned uu = su[base + r];
        if (uu > thr) {
            unsigned emin = eqb < m ? eqb : m;
            int pos = (int)(gtb + emin);
            g_idx[(size_t)bhc * WSZc + pos] = base + r;
            atomicAdd(&g_cnt[bh * Tt + base + r], 1);
            gtb++;
        } else if (uu == thr) {
            if (eqb < m) {
                int pos = (int)(gtb + eqb);
                g_idx[(size_t)bhc * WSZc + pos] = base + r;
                atomicAdd(&g_cnt[bh * Tt + base + r], 1);
            }
            eqb++;
        }
    }
}

// ---------------- kernel 3: tf32 tensor-core windowed attention ----------------
// 512 threads = 16 warps; warp w owns row-tile w (16 rows). Barrier-free
// mainloop after a single staging barrier; light warps simply retire early.
__device__ __forceinline__ unsigned f2tf(float f) {
    unsigned u;
    asm("cvt.rna.tf32.f32 %0, %1;" : "=r"(u) : "f"(f));
    return u;
}
__device__ __forceinline__ void mma8(float* d, const unsigned* a, uint2 b) {
    asm volatile("mma.sync.aligned.m16n8k8.row.col.f32.tf32.tf32.f32 "
                 "{%0,%1,%2,%3}, {%4,%5,%6,%7}, {%8,%9}, {%0,%1,%2,%3};"
                 : "+f"(d[0]), "+f"(d[1]), "+f"(d[2]), "+f"(d[3])
                 : "r"(a[0]), "r"(a[1]), "r"(a[2]), "r"(a[3]), "r"(b.x), "r"(b.y));
}

// accumulator-layout (16x8) -> A-operand layout via intra-quad shuffles
__device__ __forceinline__ void shuffle_p(const float* s, unsigned* A, int c) {
    int hq = c >> 1, e = c & 1;
    float v00 = __shfl_sync(0xffffffffu, s[0], hq, 4);
    float v01 = __shfl_sync(0xffffffffu, s[1], hq, 4);
    float v10 = __shfl_sync(0xffffffffu, s[2], hq, 4);
    float v11 = __shfl_sync(0xffffffffu, s[3], hq, 4);
    float v20 = __shfl_sync(0xffffffffu, s[0], hq + 2, 4);
    float v21 = __shfl_sync(0xffffffffu, s[1], hq + 2, 4);
    float v30 = __shfl_sync(0xffffffffu, s[2], hq + 2, 4);
    float v31 = __shfl_sync(0xffffffffu, s[3], hq + 2, 4);
    A[0] = f2tf(e ? v01 : v00);
    A[1] = f2tf(e ? v11 : v10);
    A[2] = f2tf(e ? v21 : v20);
    A[3] = f2tf(e ? v31 : v30);
}

__device__ __forceinline__ void epi_vals(int t, int jc, int nt, int g, int c,
                                         float* s, float& l0, float& l1) {
    int i0 = 16 * t + g, i1 = i0 + 8;
    int j0 = 64 * jc + 8 * nt + 2 * c, j1 = j0 + 1;
    s[0] = (j0 > i0) ? 0.f : (j0 == i0) ? ((i0 == 0) ? 1.f : 0.f) : __expf(s[0] * 0.125f);
    s[1] = (j1 > i0) ? 0.f : (j1 == i0) ? 0.f : __expf(s[1] * 0.125f);
    s[2] = (j0 > i1) ? 0.f : (j0 == i1) ? 0.f : __expf(s[2] * 0.125f);
    s[3] = (j1 > i1) ? 0.f : (j1 == i1) ? 0.f : __expf(s[3] * 0.125f);
    l0 += s[0] + s[1];
    l1 += s[2] + s[3];
}

#define KV_BUF 4096                        // u32 per chunk per operand
#define ATTN_SMEM_BYTES (8 * KV_BUF * 4)   // KF[4] + VF[4] = 128KB

__global__ void __launch_bounds__(512, 1) attn_kernel(const float* __restrict__ q,
                                                      const float* __restrict__ k,
                                                      const float* __restrict__ v,
                                                      float* __restrict__ out) {
    extern __shared__ unsigned smu[];  // [KF0..KF3, VF0..VF3]
    __shared__ int sidx[WSZc];

    int tid = threadIdx.x;
    int bhc = blockIdx.x;
    int bh = bhc >> 4;
    int w = tid >> 5, lane = tid & 31;
    int g = lane >> 2, c = lane & 3;

    if (tid < WSZc) sidx[tid] = g_idx[(size_t)bhc * WSZc + tid];
    __syncthreads();

    // ---- staging: threads 0-255 do K (normalize in-thread), 256-511 do V ----
    if (tid < 256) {
        int gj = sidx[tid];
        int jcc = tid >> 6, r = tid & 63;
        const float4* ks = (const float4*)(k + ((size_t)bh * Tt + gj) * Dd);
        unsigned* KF = smu + jcc * KV_BUF;
        int gk = r & 7, ntk = r >> 3;
        float4 kv[16];
        float ss = 0.f;
#pragma unroll
        for (int e = 0; e < 16; e++) {
            kv[e] = ks[e];
            ss += kv[e].x * kv[e].x + kv[e].y * kv[e].y +
                  kv[e].z * kv[e].z + kv[e].w * kv[e].w;
        }
        float inv = rsqrtf(ss);
#pragma unroll
        for (int e = 0; e < 16; e++) {
            int d0 = e * 4;
            int kss = d0 >> 3, half = (d0 >> 2) & 1;
            unsigned base = (unsigned)(((kss * 8 + ntk) * 32 + gk * 4) * 2 + half);
            KF[base + 0] = f2tf(kv[e].x * inv);
            KF[base + 2] = f2tf(kv[e].y * inv);
            KF[base + 4] = f2tf(kv[e].z * inv);
            KF[base + 6] = f2tf(kv[e].w * inv);
        }
    } else {
        int rr = tid - 256;
        int gj = sidx[rr];
        int jcc = rr >> 6, r = rr & 63;
        const float4* vs = (const float4*)(v + ((size_t)bh * Tt + gj) * Dd);
        unsigned* VF = smu + 4 * KV_BUF + jcc * KV_BUF;
        int ks2v = r >> 3, c0v = r & 3, halfv = (r >> 2) & 1;
#pragma unroll
        for (int e = 0; e < 16; e++) {
            float4 vv = vs[e];
            int d0 = e * 4, nt2 = d0 >> 3;
            unsigned base = (unsigned)(((ks2v * 8 + nt2) * 32 + (d0 & 7) * 4 + c0v) * 2 + halfv);
            VF[base + 0] = f2tf(vv.x);
            VF[base + 8] = f2tf(vv.y);
            VF[base + 16] = f2tf(vv.z);
            VF[base + 24] = f2tf(vv.w);
        }
    }

    // ---- Q A-fragments into registers (warp w owns tile w) ----
    unsigned A[8][4];
    {
        const float* qb = q + (size_t)bh * Tt * Dd;
        const float* r0 = qb + (size_t)sidx[16 * w + g] * Dd;
        const float* r1 = qb + (size_t)sidx[16 * w + g + 8] * Dd;
#pragma unroll
        for (int ks = 0; ks < 8; ks++) {
            A[ks][0] = f2tf(r0[8 * ks + c]);
            A[ks][1] = f2tf(r1[8 * ks + c]);
            A[ks][2] = f2tf(r0[8 * ks + c + 4]);
            A[ks][3] = f2tf(r1[8 * ks + c + 4]);
        }
    }

    float O[8][4];
#pragma unroll
    for (int nt = 0; nt < 8; nt++)
#pragma unroll
        for (int r = 0; r < 4; r++) O[nt][r] = 0.f;
    float lp[2] = {0.f, 0.f};

    __syncthreads();   // the ONLY mainloop barrier

    for (int jc = 0; jc < 4; jc++) {
        int lim = 2 * w + 1 - 8 * jc;
        if (lim < 0) break;
        const unsigned* KF = smu + jc * KV_BUF;
        const unsigned* VF = smu + 4 * KV_BUF + jc * KV_BUF;

#pragma unroll
        for (int nt = 0; nt < 8; nt++) {
            if (nt > lim) break;
            float s[4] = {0.f, 0.f, 0.f, 0.f};
#pragma unroll
            for (int ks = 0; ks < 8; ks++) {
                uint2 b = *(const uint2*)&KF[((ks * 8 + nt) * 32 + lane) * 2];
                mma8(s, A[ks], b);
            }
            epi_vals(w, jc, nt, g, c, s, lp[0], lp[1]);
            unsigned P[4];
            shuffle_p(s, P, c);
#pragma unroll
            for (int nt2 = 0; nt2 < 8; nt2++) {
                uint2 bv = *(const uint2*)&VF[((nt * 8 + nt2) * 32 + lane) * 2];
                mma8(O[nt2], P, bv);
            }
        }
    }

    // ---- row-sum reduce across quad, normalize, scatter ----
    float rs[2];
#pragma unroll
    for (int hf = 0; hf < 2; hf++) {
        float s = lp[hf];
        s += __shfl_xor_sync(0xffffffffu, s, 1);
        s += __shfl_xor_sync(0xffffffffu, s, 2);
        rs[hf] = 1.f / s;
    }
    {
        float* ob = out + (size_t)bh * Tt * Dd;
        float* o0 = ob + (size_t)sidx[16 * w + g] * Dd;
        float* o1 = ob + (size_t)sidx[16 * w + g + 8] * Dd;
#pragma unroll
        for (int nt2 = 0; nt2 < 8; nt2++) {
            int col = 8 * nt2 + 2 * c;
            atomicAdd(o0 + col, O[nt2][0] * rs[0]);
            atomicAdd(o0 + col + 1, O[nt2][1] * rs[0]);
            atomicAdd(o1 + col, O[nt2][2] * rs[1]);
            atomicAdd(o1 + col + 1, O[nt2][3] * rs[1]);
        }
    }
}

// ---------------- kernel 4: divide by count + aux loss ----------------
__global__ void finalize_kernel(float* out, int out_size) {
    const int n = Bq * Hh * Tt * Dd;
    const int n4 = n / 4;
    int i = blockIdx.x * blockDim.x + threadIdx.x;
    int stride = gridDim.x * blockDim.x;
    for (int p = i; p < n4; p += stride) {
        float4 o = ((float4*)out)[p];
        float cc = (float)g_cnt[p >> 4];
        float inv = 1.f / (cc + 1e-5f);
        o.x *= inv; o.y *= inv; o.z *= inv; o.w *= inv;
        ((float4*)out)[p] = o;
    }
    if (blockIdx.x == 0) {
        __shared__ float sred[256];
        float s = 0.f;
        for (int p = threadIdx.x; p < Bq * Hh * Tt / 8; p += 256) s += g_aux_part[p];
        sred[threadIdx.x] = s;
        __syncthreads();
        for (int off = 128; off; off >>= 1) {
            if (threadIdx.x < off) sred[threadIdx.x] += sred[threadIdx.x + off];
            __syncthreads();
        }
        if (threadIdx.x == 0 && out_size > n)
            out[n] = sred[0] * (1e-4f / (float)n);
    }
}

// ---------------- launch ----------------
extern "C" void kernel_launch(void* const* d_in, const int* in_sizes, int n_in,
                              void* d_out, int out_size) {
    const float* q = (const float*)d_in[0];
    const float* k = (const float*)d_in[1];
    const float* v = (const float*)d_in[2];
    const float* means = (const float*)d_in[3];
    float* out = (float*)d_out;

    cudaFuncSetAttribute(attn_kernel, cudaFuncAttributeMaxDynamicSharedMemorySize,
                         ATTN_SMEM_BYTES);

    route_kernel<<<Bq * Hh * Tt / 8, 256>>>(k, means);
    topk_kernel<<<Bq * Hh * NCc, 256>>>(out);
    attn_kernel<<<Bq * Hh * NCc, 512, ATTN_SMEM_BYTES>>>(q, k, v, out);
    finalize_kernel<<<2048, 256>>>(out, out_size);
}

// round 10
// speedup vs baseline: 2.8111x; 1.0231x over previous
#include <cuda_runtime.h>
#include <math.h>

#define Bq 4
#define Hh 8
#define Tt 4096
#define Dd 64
#define NCc 16
#define WSZc 256

// ---------------- scratch (no allocations allowed) ----------------
__device__ float g_dists[Bq * Hh * NCc * Tt];     // [bh, c, t], 8MB
__device__ int   g_idx[Bq * Hh * NCc * WSZc];     // sorted top-k indices
__device__ int   g_cnt[Bq * Hh * Tt];             // scatter counts
__device__ float g_aux_part[Bq * Hh * Tt / 8];    // per-route-block aux partials

// ---------------- kernel 1: route (+ zero cnt) ----------------
__global__ void route_kernel(const float* __restrict__ k,
                             const float* __restrict__ means) {
    __shared__ float sm[NCc * Dd];
    __shared__ float saux;
    __shared__ float sdl[NCc][8];

    {
        long long gid = (long long)blockIdx.x * blockDim.x + threadIdx.x;
        const long long c4 = (long long)Bq * Hh * Tt / 4;
        if (gid < c4) ((int4*)g_cnt)[gid] = make_int4(0, 0, 0, 0);
    }

    int token0 = blockIdx.x * 8;
    int bh = token0 / Tt;
    int h = bh % Hh;
    const float* mh = means + (size_t)h * NCc * Dd;
    for (int i = threadIdx.x; i < NCc * Dd; i += blockDim.x) sm[i] = mh[i];
    if (threadIdx.x == 0) saux = 0.f;
    __syncthreads();

    int warp = threadIdx.x >> 5, lane = threadIdx.x & 31;
    int token = token0 + warp;
    int t = token & (Tt - 1);

    float2 kv = ((const float2*)(k + (size_t)token * Dd))[lane];
    float ss = kv.x * kv.x + kv.y * kv.y;
#pragma unroll
    for (int o = 16; o; o >>= 1) ss += __shfl_xor_sync(0xffffffffu, ss, o);
    float inv = rsqrtf(ss);
    float2 xv = make_float2(kv.x * inv, kv.y * inv);

    float dl[NCc];
#pragma unroll
    for (int c = 0; c < NCc; c++)
        dl[c] = xv.x * sm[c * Dd + 2 * lane] + xv.y * sm[c * Dd + 2 * lane + 1];
#pragma unroll
    for (int o = 16; o; o >>= 1) {
#pragma unroll
        for (int c = 0; c < NCc; c++)
            dl[c] += __shfl_xor_sync(0xffffffffu, dl[c], o);
    }
    int bestc = 0;
    float bestv = dl[0];
#pragma unroll
    for (int c = 1; c < NCc; c++)
        if (dl[c] > bestv) { bestv = dl[c]; bestc = c; }

    if (lane == 0) {
#pragma unroll
        for (int c = 0; c < NCc; c++) sdl[c][warp] = dl[c];
    }

    float mx = sm[bestc * Dd + 2 * lane];
    float my = sm[bestc * Dd + 2 * lane + 1];
    float ex = xv.x - mx, ey = xv.y - my;
    float e = ex * ex + ey * ey;
#pragma unroll
    for (int o = 16; o; o >>= 1) e += __shfl_xor_sync(0xffffffffu, e, o);
    if (lane == 0) atomicAdd(&saux, e);
    __syncthreads();

    if (threadIdx.x < 128) {
        int c = threadIdx.x >> 3, tt = threadIdx.x & 7;
        int tbase = token0 & (Tt - 1);
        g_dists[((size_t)bh * NCc + c) * Tt + tbase + tt] = sdl[c][tt];
    }
    if (threadIdx.x == 0) g_aux_part[blockIdx.x] = saux;
}

// ---------------- kernel 2: radix-select top-WSZ per (b,h,c) (+ zero out) ----
__device__ __forceinline__ unsigned warp_incl_scan(unsigned v, int lane) {
#pragma unroll
    for (int off = 1; off < 32; off <<= 1) {
        unsigned t = __shfl_up_sync(0xffffffffu, v, off);
        if (lane >= off) v += t;
    }
    return v;
}

__device__ __forceinline__ void find_bin(unsigned* h, unsigned* wsum,
                                         unsigned* s_bin, unsigned* s_k, int tid) {
    int lane = tid & 31, w = tid >> 5;
    unsigned K = *s_k;
    unsigned tot = 0;
#pragma unroll
    for (int r = 0; r < 16; r++) tot += h[tid * 16 + r];
    unsigned p = warp_incl_scan(tot, lane);
    if (lane == 31) wsum[w] = p;
    __syncthreads();
    unsigned off = 0, S = 0;
#pragma unroll
    for (int i = 0; i < 8; i++) {
        unsigned x = wsum[i];
        S += x;
        if (i < w) off += x;
    }
    unsigned above = S - (p + off);
    unsigned run = above;
#pragma unroll
    for (int r = 15; r >= 0; r--) {
        unsigned cc = h[tid * 16 + r];
        run += cc;
        if (run >= K && run - cc < K) {
            *s_bin = (unsigned)(tid * 16 + r);
            *s_k = K - (run - cc);
        }
    }
    __syncthreads();
}

__global__ void __launch_bounds__(256) topk_kernel(float* __restrict__ out) {
    __shared__ unsigned su[Tt];
    __shared__ unsigned h[4096];
    __shared__ unsigned wsum[8];
    __shared__ unsigned s_bin, s_k;
    int tid = threadIdx.x;
    int lane = tid & 31, w = tid >> 5;
    int bhc = blockIdx.x;
    const float* dc = g_dists + (size_t)bhc * Tt;

    {
        float4* o4 = (float4*)out + (size_t)blockIdx.x * 4096;
        for (int i = tid; i < 4096; i += 256)
            o4[i] = make_float4(0.f, 0.f, 0.f, 0.f);
    }

    for (int i = tid; i < Tt; i += 256) {
        unsigned uu = __float_as_uint(dc[i]);
        uu = (uu & 0x80000000u) ? ~uu : (uu | 0x80000000u);
        su[i] = uu;
        h[i] = 0u;
    }
    if (tid == 0) s_k = WSZc;
    __syncthreads();

    for (int i = tid; i < Tt; i += 256) atomicAdd(&h[su[i] >> 20], 1u);
    __syncthreads();
    find_bin(h, wsum, &s_bin, &s_k, tid);
    unsigned b1 = s_bin;
    for (int i = tid; i < 4096; i += 256) h[i] = 0u;
    __syncthreads();

    for (int i = tid; i < Tt; i += 256)
        if ((su[i] >> 20) == b1) atomicAdd(&h[(su[i] >> 8) & 0xFFFu], 1u);
    __syncthreads();
    find_bin(h, wsum, &s_bin, &s_k, tid);
    unsigned b2 = s_bin;
    for (int i = tid; i < 4096; i += 256) h[i] = 0u;
    __syncthreads();

    unsigned hi20 = (b1 << 12) | b2;
    for (int i = tid; i < Tt; i += 256)
        if ((su[i] >> 8) == hi20) atomicAdd(&h[su[i] & 0xFFu], 1u);
    __syncthreads();
    find_bin(h, wsum, &s_bin, &s_k, tid);
    unsigned b3 = s_bin;
    unsigned m = s_k;
    unsigned thr = (b1 << 20) | (b2 << 8) | b3;

    unsigned gt = 0, eq = 0;
    int base = tid * 16;
#pragma unroll
    for (int r = 0; r < 16; r++) {
        unsigned uu = su[base + r];
        gt += (uu > thr);
        eq += (uu == thr);
    }
    unsigned mypack = (gt << 16) | eq;
    unsigned p = warp_incl_scan(mypack, lane);
    if (lane == 31) wsum[w] = p;
    __syncthreads();
    unsigned off = 0;
#pragma unroll
    for (int i = 0; i < 8; i++)
        if (i < w) off += wsum[i];
    unsigned excl = p + off - mypack;
    unsigned gtb = excl >> 16, eqb = excl & 0xFFFFu;
    int bh = bhc >> 4;
#pragma unroll
    for (int r = 0; r < 16; r++) {
        unsigned uu = su[base + r];
        if (uu > thr) {
            unsigned emin = eqb < m ? eqb : m;
            int pos = (int)(gtb + emin);
            g_idx[(size_t)bhc * WSZc + pos] = base + r;
            atomicAdd(&g_cnt[bh * Tt + base + r], 1);
            gtb++;
        } else if (uu == thr) {
            if (eqb < m) {
                int pos = (int)(gtb + eqb);
                g_idx[(size_t)bhc * WSZc + pos] = base + r;
                atomicAdd(&g_cnt[bh * Tt + base + r], 1);
            }
            eqb++;
        }
    }
}

// ---------------- kernel 3: tf32 tensor-core windowed attention ----------------
// 512 threads = 16 warps; warp w owns row-tile w. Barrier-free mainloop.
// ILP: dual-nt processing + split-K accumulators (chain depth 8 -> 4).
__device__ __forceinline__ unsigned f2tf(float f) {
    unsigned u;
    asm("cvt.rna.tf32.f32 %0, %1;" : "=r"(u) : "f"(f));
    return u;
}
__device__ __forceinline__ void mma8(float* d, const unsigned* a, uint2 b) {
    asm volatile("mma.sync.aligned.m16n8k8.row.col.f32.tf32.tf32.f32 "
                 "{%0,%1,%2,%3}, {%4,%5,%6,%7}, {%8,%9}, {%0,%1,%2,%3};"
                 : "+f"(d[0]), "+f"(d[1]), "+f"(d[2]), "+f"(d[3])
                 : "r"(a[0]), "r"(a[1]), "r"(a[2]), "r"(a[3]), "r"(b.x), "r"(b.y));
}

// accumulator-layout (16x8) -> A-operand layout via intra-quad shuffles
__device__ __forceinline__ void shuffle_p(const float* s, unsigned* A, int c) {
    int hq = c >> 1, e = c & 1;
    float v00 = __shfl_sync(0xffffffffu, s[0], hq, 4);
    float v01 = __shfl_sync(0xffffffffu, s[1], hq, 4);
    float v10 = __shfl_sync(0xffffffffu, s[2], hq, 4);
    float v11 = __shfl_sync(0xffffffffu, s[3], hq, 4);
    float v20 = __shfl_sync(0xffffffffu, s[0], hq + 2, 4);
    float v21 = __shfl_sync(0xffffffffu, s[1], hq + 2, 4);
    float v30 = __shfl_sync(0xffffffffu, s[2], hq + 2, 4);
    float v31 = __shfl_sync(0xffffffffu, s[3], hq + 2, 4);
    A[0] = f2tf(e ? v01 : v00);
    A[1] = f2tf(e ? v11 : v10);
    A[2] = f2tf(e ? v21 : v20);
    A[3] = f2tf(e ? v31 : v30);
}

__device__ __forceinline__ void epi_vals(int t, int jc, int nt, int g, int c,
                                         float* s, float& l0, float& l1) {
    int i0 = 16 * t + g, i1 = i0 + 8;
    int j0 = 64 * jc + 8 * nt + 2 * c, j1 = j0 + 1;
    s[0] = (j0 > i0) ? 0.f : (j0 == i0) ? ((i0 == 0) ? 1.f : 0.f) : __expf(s[0] * 0.125f);
    s[1] = (j1 > i0) ? 0.f : (j1 == i0) ? 0.f : __expf(s[1] * 0.125f);
    s[2] = (j0 > i1) ? 0.f : (j0 == i1) ? 0.f : __expf(s[2] * 0.125f);
    s[3] = (j1 > i1) ? 0.f : (j1 == i1) ? 0.f : __expf(s[3] * 0.125f);
    l0 += s[0] + s[1];
    l1 += s[2] + s[3];
}

#define KV_BUF 4096                        // u32 per chunk per operand
#define ATTN_SMEM_BYTES (8 * KV_BUF * 4)   // KF[4] + VF[4] = 128KB

__global__ void __launch_bounds__(512, 1) attn_kernel(const float* __restrict__ q,
                                                      const float* __restrict__ k,
                                                      const float* __restrict__ v,
                                                      float* __restrict__ out) {
    extern __shared__ unsigned smu[];  // [KF0..KF3, VF0..VF3]
    __shared__ int sidx[WSZc];

    int tid = threadIdx.x;
    int bhc = blockIdx.x;
    int bh = bhc >> 4;
    int w = tid >> 5, lane = tid & 31;
    int g = lane >> 2, c = lane & 3;

    if (tid < WSZc) sidx[tid] = g_idx[(size_t)bhc * WSZc + tid];
    __syncthreads();

    // ---- staging: threads 0-255 do K (normalize in-thread), 256-511 do V ----
    if (tid < 256) {
        int gj = sidx[tid];
        int jcc = tid >> 6, r = tid & 63;
        const float4* ks = (const float4*)(k + ((size_t)bh * Tt + gj) * Dd);
        unsigned* KF = smu + jcc * KV_BUF;
        int gk = r & 7, ntk = r >> 3;
        float4 kv[16];
        float ss = 0.f;
#pragma unroll
        for (int e = 0; e < 16; e++) {
            kv[e] = ks[e];
            ss += kv[e].x * kv[e].x + kv[e].y * kv[e].y +
                  kv[e].z * kv[e].z + kv[e].w * kv[e].w;
        }
        float inv = rsqrtf(ss);
#pragma unroll
        for (int e = 0; e < 16; e++) {
            int d0 = e * 4;
            int kss = d0 >> 3, half = (d0 >> 2) & 1;
            unsigned base = (unsigned)(((kss * 8 + ntk) * 32 + gk * 4) * 2 + half);
            KF[base + 0] = f2tf(kv[e].x * inv);
            KF[base + 2] = f2tf(kv[e].y * inv);
            KF[base + 4] = f2tf(kv[e].z * inv);
            KF[base + 6] = f2tf(kv[e].w * inv);
        }
    } else {
        int rr = tid - 256;
        int gj = sidx[rr];
        int jcc = rr >> 6, r = rr & 63;
        const float4* vs = (const float4*)(v + ((size_t)bh * Tt + gj) * Dd);
        unsigned* VF = smu + 4 * KV_BUF + jcc * KV_BUF;
        int ks2v = r >> 3, c0v = r & 3, halfv = (r >> 2) & 1;
#pragma unroll
        for (int e = 0; e < 16; e++) {
            float4 vv = vs[e];
            int d0 = e * 4, nt2 = d0 >> 3;
            unsigned base = (unsigned)(((ks2v * 8 + nt2) * 32 + (d0 & 7) * 4 + c0v) * 2 + halfv);
            VF[base + 0] = f2tf(vv.x);
            VF[base + 8] = f2tf(vv.y);
            VF[base + 16] = f2tf(vv.z);
            VF[base + 24] = f2tf(vv.w);
        }
    }

    // ---- Q A-fragments into registers (warp w owns tile w) ----
    unsigned A[8][4];
    {
        const float* qb = q + (size_t)bh * Tt * Dd;
        const float* r0 = qb + (size_t)sidx[16 * w + g] * Dd;
        const float* r1 = qb + (size_t)sidx[16 * w + g + 8] * Dd;
#pragma unroll
        for (int ks = 0; ks < 8; ks++) {
            A[ks][0] = f2tf(r0[8 * ks + c]);
            A[ks][1] = f2tf(r1[8 * ks + c]);
            A[ks][2] = f2tf(r0[8 * ks + c + 4]);
            A[ks][3] = f2tf(r1[8 * ks + c + 4]);
        }
    }

    float O[8][4];
#pragma unroll
    for (int nt = 0; nt < 8; nt++)
#pragma unroll
        for (int r = 0; r < 4; r++) O[nt][r] = 0.f;
    float lp[2] = {0.f, 0.f};

    __syncthreads();   // the ONLY mainloop barrier

    for (int jc = 0; jc < 4; jc++) {
        int lim = 2 * w + 1 - 8 * jc;
        if (lim < 0) break;
        const unsigned* KF = smu + jc * KV_BUF;
        const unsigned* VF = smu + 4 * KV_BUF + jc * KV_BUF;

        // dual-nt + split-K: 4 independent mma chains of depth 4 in GEMM1
#pragma unroll
        for (int nt = 0; nt < 8; nt += 2) {
            if (nt > lim) break;
            bool two = (nt + 1 <= lim);
            float sa[4] = {0.f, 0.f, 0.f, 0.f};  // nt,  ks 0-3
            float sb[4] = {0.f, 0.f, 0.f, 0.f};  // nt,  ks 4-7
            float sc[4] = {0.f, 0.f, 0.f, 0.f};  // nt+1, ks 0-3
            float sd[4] = {0.f, 0.f, 0.f, 0.f};  // nt+1, ks 4-7
#pragma unroll
            for (int ks = 0; ks < 4; ks++) {
                uint2 b0 = *(const uint2*)&KF[((ks * 8 + nt) * 32 + lane) * 2];
                uint2 b1 = *(const uint2*)&KF[(((ks + 4) * 8 + nt) * 32 + lane) * 2];
                mma8(sa, A[ks], b0);
                mma8(sb, A[ks + 4], b1);
                if (two) {
                    uint2 b2 = *(const uint2*)&KF[((ks * 8 + nt + 1) * 32 + lane) * 2];
                    uint2 b3 = *(const uint2*)&KF[(((ks + 4) * 8 + nt + 1) * 32 + lane) * 2];
                    mma8(sc, A[ks], b2);
                    mma8(sd, A[ks + 4], b3);
                }
            }
#pragma unroll
            for (int r = 0; r < 4; r++) { sa[r] += sb[r]; sc[r] += sd[r]; }

            epi_vals(w, jc, nt, g, c, sa, lp[0], lp[1]);
            unsigned P0[4], P1[4];
            shuffle_p(sa, P0, c);
            if (two) {
                epi_vals(w, jc, nt + 1, g, c, sc, lp[0], lp[1]);
                shuffle_p(sc, P1, c);
            }
#pragma unroll
            for (int nt2 = 0; nt2 < 8; nt2++) {
                uint2 bv0 = *(const uint2*)&VF[((nt * 8 + nt2) * 32 + lane) * 2];
                mma8(O[nt2], P0, bv0);
                if (two) {
                    uint2 bv1 = *(const uint2*)&VF[(((nt + 1) * 8 + nt2) * 32 + lane) * 2];
                    mma8(O[nt2], P1, bv1);
                }
            }
        }
    }

    // ---- row-sum reduce across quad, normalize, scatter ----
    float rs[2];
#pragma unroll
    for (int hf = 0; hf < 2; hf++) {
        float s = lp[hf];
        s += __shfl_xor_sync(0xffffffffu, s, 1);
        s += __shfl_xor_sync(0xffffffffu, s, 2);
        rs[hf] = 1.f / s;
    }
    {
        float* ob = out + (size_t)bh * Tt * Dd;
        float* o0 = ob + (size_t)sidx[16 * w + g] * Dd;
        float* o1 = ob + (size_t)sidx[16 * w + g + 8] * Dd;
#pragma unroll
        for (int nt2 = 0; nt2 < 8; nt2++) {
            int col = 8 * nt2 + 2 * c;
            atomicAdd(o0 + col, O[nt2][0] * rs[0]);
            atomicAdd(o0 + col + 1, O[nt2][1] * rs[0]);
            atomicAdd(o1 + col, O[nt2][2] * rs[1]);
            atomicAdd(o1 + col + 1, O[nt2][3] * rs[1]);
        }
    }
}

// ---------------- kernel 4: divide by count + aux loss ----------------
__global__ void finalize_kernel(float* out, int out_size) {
    const int n = Bq * Hh * Tt * Dd;
    const int n4 = n / 4;
    int i = blockIdx.x * blockDim.x + threadIdx.x;
    int stride = gridDim.x * blockDim.x;
    for (int p = i; p < n4; p += stride) {
        float4 o = ((float4*)out)[p];
        float cc = (float)g_cnt[p >> 4];
        float inv = 1.f / (cc + 1e-5f);
        o.x *= inv; o.y *= inv; o.z *= inv; o.w *= inv;
        ((float4*)out)[p] = o;
    }
    if (blockIdx.x == 0) {
        __shared__ float sred[256];
        float s = 0.f;
        for (int p = threadIdx.x; p < Bq * Hh * Tt / 8; p += 256) s += g_aux_part[p];
        sred[threadIdx.x] = s;
        __syncthreads();
        for (int off = 128; off; off >>= 1) {
            if (threadIdx.x < off) sred[threadIdx.x] += sred[threadIdx.x + off];
            __syncthreads();
        }
        if (threadIdx.x == 0 && out_size > n)
            out[n] = sred[0] * (1e-4f / (float)n);
    }
}

// ---------------- launch ----------------
extern "C" void kernel_launch(void* const* d_in, const int* in_sizes, int n_in,
                              void* d_out, int out_size) {
    const float* q = (const float*)d_in[0];
    const float* k = (const float*)d_in[1];
    const float* v = (const float*)d_in[2];
    const float* means = (const float*)d_in[3];
    float* out = (float*)d_out;

    cudaFuncSetAttribute(attn_kernel, cudaFuncAttributeMaxDynamicSharedMemorySize,
                         ATTN_SMEM_BYTES);

    route_kernel<<<Bq * Hh * Tt / 8, 256>>>(k, means);
    topk_kernel<<<Bq * Hh * NCc, 256>>>(out);
    attn_kernel<<<Bq * Hh * NCc, 512, ATTN_SMEM_BYTES>>>(q, k, v, out);
    finalize_kernel<<<2048, 256>>>(out, out_size);
}

// round 11
// speedup vs baseline: 3.1306x; 1.1137x over previous
#include <cuda_runtime.h>
#include <math.h>

#define Bq 4
#define Hh 8
#define Tt 4096
#define Dd 64
#define NCc 16
#define WSZc 256

// ---------------- scratch (no allocations allowed) ----------------
__device__ float g_dists[Bq * Hh * NCc * Tt];     // [bh, c, t], 8MB
__device__ int   g_idx[Bq * Hh * NCc * WSZc];     // sorted top-k indices
__device__ int   g_cnt[Bq * Hh * Tt];             // scatter counts
__device__ float g_aux_part[Bq * Hh * Tt / 8];    // per-route-block aux partials

// ---------------- kernel 1: route (+ zero cnt) ----------------
__global__ void route_kernel(const float* __restrict__ k,
                             const float* __restrict__ means) {
    __shared__ float sm[NCc * Dd];
    __shared__ float saux;
    __shared__ float sdl[NCc][8];

    {
        long long gid = (long long)blockIdx.x * blockDim.x + threadIdx.x;
        const long long c4 = (long long)Bq * Hh * Tt / 4;
        if (gid < c4) ((int4*)g_cnt)[gid] = make_int4(0, 0, 0, 0);
    }

    int token0 = blockIdx.x * 8;
    int bh = token0 / Tt;
    int h = bh % Hh;
    const float* mh = means + (size_t)h * NCc * Dd;
    for (int i = threadIdx.x; i < NCc * Dd; i += blockDim.x) sm[i] = mh[i];
    if (threadIdx.x == 0) saux = 0.f;
    __syncthreads();

    int warp = threadIdx.x >> 5, lane = threadIdx.x & 31;
    int token = token0 + warp;
    int t = token & (Tt - 1);

    float2 kv = ((const float2*)(k + (size_t)token * Dd))[lane];
    float ss = kv.x * kv.x + kv.y * kv.y;
#pragma unroll
    for (int o = 16; o; o >>= 1) ss += __shfl_xor_sync(0xffffffffu, ss, o);
    float inv = rsqrtf(ss);
    float2 xv = make_float2(kv.x * inv, kv.y * inv);

    float dl[NCc];
#pragma unroll
    for (int c = 0; c < NCc; c++)
        dl[c] = xv.x * sm[c * Dd + 2 * lane] + xv.y * sm[c * Dd + 2 * lane + 1];
#pragma unroll
    for (int o = 16; o; o >>= 1) {
#pragma unroll
        for (int c = 0; c < NCc; c++)
            dl[c] += __shfl_xor_sync(0xffffffffu, dl[c], o);
    }
    int bestc = 0;
    float bestv = dl[0];
#pragma unroll
    for (int c = 1; c < NCc; c++)
        if (dl[c] > bestv) { bestv = dl[c]; bestc = c; }

    if (lane == 0) {
#pragma unroll
        for (int c = 0; c < NCc; c++) sdl[c][warp] = dl[c];
    }

    float mx = sm[bestc * Dd + 2 * lane];
    float my = sm[bestc * Dd + 2 * lane + 1];
    float ex = xv.x - mx, ey = xv.y - my;
    float e = ex * ex + ey * ey;
#pragma unroll
    for (int o = 16; o; o >>= 1) e += __shfl_xor_sync(0xffffffffu, e, o);
    if (lane == 0) atomicAdd(&saux, e);
    __syncthreads();

    if (threadIdx.x < 128) {
        int c = threadIdx.x >> 3, tt = threadIdx.x & 7;
        int tbase = token0 & (Tt - 1);
        g_dists[((size_t)bh * NCc + c) * Tt + tbase + tt] = sdl[c][tt];
    }
    if (threadIdx.x == 0) g_aux_part[blockIdx.x] = saux;
}

// ---------------- kernel 2: radix-select top-WSZ per (b,h,c) (+ zero out) ----
__device__ __forceinline__ unsigned warp_incl_scan(unsigned v, int lane) {
#pragma unroll
    for (int off = 1; off < 32; off <<= 1) {
        unsigned t = __shfl_up_sync(0xffffffffu, v, off);
        if (lane >= off) v += t;
    }
    return v;
}

__device__ __forceinline__ void find_bin(unsigned* h, unsigned* wsum,
                                         unsigned* s_bin, unsigned* s_k, int tid) {
    int lane = tid & 31, w = tid >> 5;
    unsigned K = *s_k;
    unsigned tot = 0;
#pragma unroll
    for (int r = 0; r < 16; r++) tot += h[tid * 16 + r];
    unsigned p = warp_incl_scan(tot, lane);
    if (lane == 31) wsum[w] = p;
    __syncthreads();
    unsigned off = 0, S = 0;
#pragma unroll
    for (int i = 0; i < 8; i++) {
        unsigned x = wsum[i];
        S += x;
        if (i < w) off += x;
    }
    unsigned above = S - (p + off);
    unsigned run = above;
#pragma unroll
    for (int r = 15; r >= 0; r--) {
        unsigned cc = h[tid * 16 + r];
        run += cc;
        if (run >= K && run - cc < K) {
            *s_bin = (unsigned)(tid * 16 + r);
            *s_k = K - (run - cc);
        }
    }
    __syncthreads();
}

__global__ void __launch_bounds__(256) topk_kernel(float* __restrict__ out) {
    __shared__ unsigned su[Tt];
    __shared__ unsigned h[4096];
    __shared__ unsigned wsum[8];
    __shared__ unsigned s_bin, s_k;
    int tid = threadIdx.x;
    int lane = tid & 31, w = tid >> 5;
    int bhc = blockIdx.x;
    const float* dc = g_dists + (size_t)bhc * Tt;

    {
        float4* o4 = (float4*)out + (size_t)blockIdx.x * 4096;
        for (int i = tid; i < 4096; i += 256)
            o4[i] = make_float4(0.f, 0.f, 0.f, 0.f);
    }

    for (int i = tid; i < Tt; i += 256) {
        unsigned uu = __float_as_uint(dc[i]);
        uu = (uu & 0x80000000u) ? ~uu : (uu | 0x80000000u);
        su[i] = uu;
        h[i] = 0u;
    }
    if (tid == 0) s_k = WSZc;
    __syncthreads();

    for (int i = tid; i < Tt; i += 256) atomicAdd(&h[su[i] >> 20], 1u);
    __syncthreads();
    find_bin(h, wsum, &s_bin, &s_k, tid);
    unsigned b1 = s_bin;
    for (int i = tid; i < 4096; i += 256) h[i] = 0u;
    __syncthreads();

    for (int i = tid; i < Tt; i += 256)
        if ((su[i] >> 20) == b1) atomicAdd(&h[(su[i] >> 8) & 0xFFFu], 1u);
    __syncthreads();
    find_bin(h, wsum, &s_bin, &s_k, tid);
    unsigned b2 = s_bin;
    for (int i = tid; i < 4096; i += 256) h[i] = 0u;
    __syncthreads();

    unsigned hi20 = (b1 << 12) | b2;
    for (int i = tid; i < Tt; i += 256)
        if ((su[i] >> 8) == hi20) atomicAdd(&h[su[i] & 0xFFu], 1u);
    __syncthreads();
    find_bin(h, wsum, &s_bin, &s_k, tid);
    unsigned b3 = s_bin;
    unsigned m = s_k;
    unsigned thr = (b1 << 20) | (b2 << 8) | b3;

    unsigned gt = 0, eq = 0;
    int base = tid * 16;
#pragma unroll
    for (int r = 0; r < 16; r++) {
        unsigned uu = su[base + r];
        gt += (uu > thr);
        eq += (uu == thr);
    }
    unsigned mypack = (gt << 16) | eq;
    unsigned p = warp_incl_scan(mypack, lane);
    if (lane == 31) wsum[w] = p;
    __syncthreads();
    unsigned off = 0;
#pragma unroll
    for (int i = 0; i < 8; i++)
        if (i < w) off += wsum[i];
    unsigned excl = p + off - mypack;
    unsigned gtb = excl >> 16, eqb = excl & 0xFFFFu;
    int bh = bhc >> 4;
#pragma unroll
    for (int r = 0; r < 16; r++) {
        unsigned uu = su[base + r];
        if (uu > thr) {
            unsigned emin = eqb < m ? eqb : m;
            int pos = (int)(gtb + emin);
            g_idx[(size_t)bhc * WSZc + pos] = base + r;
            atomicAdd(&g_cnt[bh * Tt + base + r], 1);
            gtb++;
        } else if (uu == thr) {
            if (eqb < m) {
                int pos = (int)(gtb + eqb);
                g_idx[(size_t)bhc * WSZc + pos] = base + r;
                atomicAdd(&g_cnt[bh * Tt + base + r], 1);
            }
            eqb++;
        }
    }
}

// ---------------- kernel 3: fp16 m16n8k16 tensor-core windowed attention -----
// 512 threads = 16 warps; warp w owns row-tile w. Barrier-free mainloop.
// fp16 k16 mma: half the mma count of tf32 k8; P accumulator pair packs
// DIRECTLY into the next GEMM's A-fragment (no shuffles).
__device__ __forceinline__ unsigned pack2h(float lo, float hi) {
    unsigned u;
    asm("cvt.rn.f16x2.f32 %0, %1, %2;" : "=r"(u) : "f"(hi), "f"(lo));
    return u;
}
__device__ __forceinline__ unsigned short f2h(float f) {
    unsigned short h;
    asm("cvt.rn.f16.f32 %0, %1;" : "=h"(h) : "f"(f));
    return h;
}
__device__ __forceinline__ void mma16(float* d, const unsigned* a, uint2 b) {
    asm volatile("mma.sync.aligned.m16n8k16.row.col.f32.f16.f16.f32 "
                 "{%0,%1,%2,%3}, {%4,%5,%6,%7}, {%8,%9}, {%0,%1,%2,%3};"
                 : "+f"(d[0]), "+f"(d[1]), "+f"(d[2]), "+f"(d[3])
                 : "r"(a[0]), "r"(a[1]), "r"(a[2]), "r"(a[3]), "r"(b.x), "r"(b.y));
}

__device__ __forceinline__ void epi_vals(int t, int jc, int nt, int g, int c,
                                         float* s, float& l0, float& l1) {
    int i0 = 16 * t + g, i1 = i0 + 8;
    int j0 = 64 * jc + 8 * nt + 2 * c, j1 = j0 + 1;
    s[0] = (j0 > i0) ? 0.f : (j0 == i0) ? ((i0 == 0) ? 1.f : 0.f) : __expf(s[0] * 0.125f);
    s[1] = (j1 > i0) ? 0.f : (j1 == i0) ? 0.f : __expf(s[1] * 0.125f);
    s[2] = (j0 > i1) ? 0.f : (j0 == i1) ? 0.f : __expf(s[2] * 0.125f);
    s[3] = (j1 > i1) ? 0.f : (j1 == i1) ? 0.f : __expf(s[3] * 0.125f);
    l0 += s[0] + s[1];
    l1 += s[2] + s[3];
}

#define KV_BUF 2048                        // u32 per chunk per operand (fp16)
#define ATTN_SMEM_BYTES (8 * KV_BUF * 4)   // KF[4] + VF[4] = 64KB

__global__ void __launch_bounds__(512, 1) attn_kernel(const float* __restrict__ q,
                                                      const float* __restrict__ k,
                                                      const float* __restrict__ v,
                                                      float* __restrict__ out) {
    extern __shared__ unsigned smu[];  // [KF0..KF3, VF0..VF3]
    __shared__ int sidx[WSZc];

    int tid = threadIdx.x;
    int bhc = blockIdx.x;
    int bh = bhc >> 4;
    int w = tid >> 5, lane = tid & 31;
    int g = lane >> 2, c = lane & 3;

    if (tid < WSZc) sidx[tid] = g_idx[(size_t)bhc * WSZc + tid];
    __syncthreads();

    // ---- staging: threads 0-255 K (normalize in-thread), 256-511 V ----
    if (tid < 256) {
        int gj = sidx[tid];
        int jcc = tid >> 6, r = tid & 63;
        const float4* ks4 = (const float4*)(k + ((size_t)bh * Tt + gj) * Dd);
        unsigned* KF = smu + jcc * KV_BUF;
        int nt = r >> 3, gk = r & 7;
        float4 kv[16];
        float ss = 0.f;
#pragma unroll
        for (int e = 0; e < 16; e++) {
            kv[e] = ks4[e];
            ss += kv[e].x * kv[e].x + kv[e].y * kv[e].y +
                  kv[e].z * kv[e].z + kv[e].w * kv[e].w;
        }
        float inv = rsqrtf(ss);
        // KF B-frag: reg0 = {kn[16ks+2c], kn[16ks+2c+1]}, reg1 = d+8
#pragma unroll
        for (int ks = 0; ks < 4; ks++) {
#pragma unroll
            for (int cc = 0; cc < 4; cc++) {
                int e0 = 4 * ks + (cc >> 1);
                float lo0, hi0, lo1, hi1;
                if (cc & 1) {
                    lo0 = kv[e0].z; hi0 = kv[e0].w;
                    lo1 = kv[e0 + 2].z; hi1 = kv[e0 + 2].w;
                } else {
                    lo0 = kv[e0].x; hi0 = kv[e0].y;
                    lo1 = kv[e0 + 2].x; hi1 = kv[e0 + 2].y;
                }
                unsigned r0 = pack2h(lo0 * inv, hi0 * inv);
                unsigned r1 = pack2h(lo1 * inv, hi1 * inv);
                *(uint2*)&KF[((ks * 8 + nt) * 32 + gk * 4 + cc) * 2] = make_uint2(r0, r1);
            }
        }
    } else {
        int rr = tid - 256;
        int gj = sidx[rr];
        int jcc = rr >> 6, r = rr & 63;
        const float4* vs4 = (const float4*)(v + ((size_t)bh * Tt + gj) * Dd);
        unsigned short* VH = (unsigned short*)(smu + 4 * KV_BUF + jcc * KV_BUF);
        // key r within chunk: kg = r>>4, position-in-16: reg*8 + 2c + p
        int kg = r >> 4, rloc = r & 15;
        int reg = (rloc >> 3) & 1, cc = (rloc & 7) >> 1, p = rloc & 1;
#pragma unroll
        for (int e = 0; e < 16; e++) {
            float4 vv = vs4[e];
            float vals[4] = {vv.x, vv.y, vv.z, vv.w};
#pragma unroll
            for (int j = 0; j < 4; j++) {
                int d = e * 4 + j;
                int nt2 = d >> 3, gv = d & 7;
                int addr32 = ((kg * 8 + nt2) * 32 + gv * 4 + cc) * 2 + reg;
                VH[addr32 * 2 + p] = f2h(vals[j]);
            }
        }
    }

    // ---- Q A-fragments (fp16) into registers (warp w owns tile w) ----
    unsigned A[4][4];
    {
        const float* qb = q + (size_t)bh * Tt * Dd;
        const float* r0 = qb + (size_t)sidx[16 * w + g] * Dd;
        const float* r1 = qb + (size_t)sidx[16 * w + g + 8] * Dd;
#pragma unroll
        for (int ks = 0; ks < 4; ks++) {
            int d0 = 16 * ks + 2 * c;
            A[ks][0] = pack2h(r0[d0], r0[d0 + 1]);
            A[ks][1] = pack2h(r1[d0], r1[d0 + 1]);
            A[ks][2] = pack2h(r0[d0 + 8], r0[d0 + 9]);
            A[ks][3] = pack2h(r1[d0 + 8], r1[d0 + 9]);
        }
    }

    float O[8][4];
#pragma unroll
    for (int nt = 0; nt < 8; nt++)
#pragma unroll
        for (int r = 0; r < 4; r++) O[nt][r] = 0.f;
    float lp[2] = {0.f, 0.f};

    __syncthreads();   // the ONLY mainloop barrier

    for (int jc = 0; jc < 4; jc++) {
        int lim = 2 * w + 1 - 8 * jc;
        if (lim < 0) break;
        const unsigned* KF = smu + jc * KV_BUF;
        const unsigned* VF = smu + 4 * KV_BUF + jc * KV_BUF;

#pragma unroll
        for (int nt = 0; nt < 8; nt += 2) {
            if (nt > lim) break;
            bool two = (nt + 1 <= lim);
            float sa[4] = {0.f, 0.f, 0.f, 0.f};  // nt,   ks 0-1
            float sb[4] = {0.f, 0.f, 0.f, 0.f};  // nt,   ks 2-3
            float sc[4] = {0.f, 0.f, 0.f, 0.f};  // nt+1, ks 0-1
            float sd[4] = {0.f, 0.f, 0.f, 0.f};  // nt+1, ks 2-3
#pragma unroll
            for (int ks = 0; ks < 2; ks++) {
                uint2 b0 = *(const uint2*)&KF[((ks * 8 + nt) * 32 + lane) * 2];
                uint2 b1 = *(const uint2*)&KF[(((ks + 2) * 8 + nt) * 32 + lane) * 2];
                mma16(sa, A[ks], b0);
                mma16(sb, A[ks + 2], b1);
                if (two) {
                    uint2 b2 = *(const uint2*)&KF[((ks * 8 + nt + 1) * 32 + lane) * 2];
                    uint2 b3 = *(const uint2*)&KF[(((ks + 2) * 8 + nt + 1) * 32 + lane) * 2];
                    mma16(sc, A[ks], b2);
                    mma16(sd, A[ks + 2], b3);
                }
            }
#pragma unroll
            for (int r = 0; r < 4; r++) { sa[r] += sb[r]; sc[r] += sd[r]; }

            epi_vals(w, jc, nt, g, c, sa, lp[0], lp[1]);
            if (two) epi_vals(w, jc, nt + 1, g, c, sc, lp[0], lp[1]);
            // else sc stays all-zero -> contributes nothing

            // P 16x16 A-fragment = the two accumulators packed (no shuffles)
            unsigned P[4];
            P[0] = pack2h(sa[0], sa[1]);
            P[1] = pack2h(sa[2], sa[3]);
            P[2] = pack2h(sc[0], sc[1]);
            P[3] = pack2h(sc[2], sc[3]);

            int kg = nt >> 1;
#pragma unroll
            for (int nt2 = 0; nt2 < 8; nt2++) {
                uint2 bv = *(const uint2*)&VF[((kg * 8 + nt2) * 32 + lane) * 2];
                mma16(O[nt2], P, bv);
            }
        }
    }

    // ---- row-sum reduce across quad, normalize, scatter ----
    float rs[2];
#pragma unroll
    for (int hf = 0; hf < 2; hf++) {
        float s = lp[hf];
        s += __shfl_xor_sync(0xffffffffu, s, 1);
        s += __shfl_xor_sync(0xffffffffu, s, 2);
        rs[hf] = 1.f / s;
    }
    {
        float* ob = out + (size_t)bh * Tt * Dd;
        float* o0 = ob + (size_t)sidx[16 * w + g] * Dd;
        float* o1 = ob + (size_t)sidx[16 * w + g + 8] * Dd;
#pragma unroll
        for (int nt2 = 0; nt2 < 8; nt2++) {
            int col = 8 * nt2 + 2 * c;
            atomicAdd(o0 + col, O[nt2][0] * rs[0]);
            atomicAdd(o0 + col + 1, O[nt2][1] * rs[0]);
            atomicAdd(o1 + col, O[nt2][2] * rs[1]);
            atomicAdd(o1 + col + 1, O[nt2][3] * rs[1]);
        }
    }
}

// ---------------- kernel 4: divide by count + aux loss ----------------
__global__ void finalize_kernel(float* out, int out_size) {
    const int n = Bq * Hh * Tt * Dd;
    const int n4 = n / 4;
    int i = blockIdx.x * blockDim.x + threadIdx.x;
    int stride = gridDim.x * blockDim.x;
    for (int p = i; p < n4; p += stride) {
        float4 o = ((float4*)out)[p];
        float cc = (float)g_cnt[p >> 4];
        float inv = 1.f / (cc + 1e-5f);
        o.x *= inv; o.y *= inv; o.z *= inv; o.w *= inv;
        ((float4*)out)[p] = o;
    }
    if (blockIdx.x == 0) {
        __shared__ float sred[256];
        float s = 0.f;
        for (int p = threadIdx.x; p < Bq * Hh * Tt / 8; p += 256) s += g_aux_part[p];
        sred[threadIdx.x] = s;
        __syncthreads();
        for (int off = 128; off; off >>= 1) {
            if (threadIdx.x < off) sred[threadIdx.x] += sred[threadIdx.x + off];
            __syncthreads();
        }
        if (threadIdx.x == 0 && out_size > n)
            out[n] = sred[0] * (1e-4f / (float)n);
    }
}

// ---------------- launch ----------------
extern "C" void kernel_launch(void* const* d_in, const int* in_sizes, int n_in,
                              void* d_out, int out_size) {
    const float* q = (const float*)d_in[0];
    const float* k = (const float*)d_in[1];
    const float* v = (const float*)d_in[2];
    const float* means = (const float*)d_in[3];
    float* out = (float*)d_out;

    cudaFuncSetAttribute(attn_kernel, cudaFuncAttributeMaxDynamicSharedMemorySize,
                         ATTN_SMEM_BYTES);

    route_kernel<<<Bq * Hh * Tt / 8, 256>>>(k, means);
    topk_kernel<<<Bq * Hh * NCc, 256>>>(out);
    attn_kernel<<<Bq * Hh * NCc, 512, ATTN_SMEM_BYTES>>>(q, k, v, out);
    finalize_kernel<<<2048, 256>>>(out, out_size);
}

// round 13
// speedup vs baseline: 3.1614x; 1.0098x over previous
#include <cuda_runtime.h>
#include <math.h>

#define Bq 4
#define Hh 8
#define Tt 4096
#define Dd 64
#define NCc 16
#define WSZc 256

// ---------------- scratch (no allocations allowed) ----------------
__device__ float g_dists[Bq * Hh * NCc * Tt];     // [bh, c, t], 8MB
__device__ int   g_idx[Bq * Hh * NCc * WSZc];     // sorted top-k indices
__device__ int   g_cnt[Bq * Hh * Tt];             // scatter counts
__device__ float g_aux_part[Bq * Hh * Tt / 8];    // per-route-block aux partials

// ---------------- kernel 1: route (+ zero cnt) ----------------
__global__ void route_kernel(const float* __restrict__ k,
                             const float* __restrict__ means) {
    __shared__ float sm[NCc * Dd];
    __shared__ float saux;
    __shared__ float sdl[NCc][8];

    {
        long long gid = (long long)blockIdx.x * blockDim.x + threadIdx.x;
        const long long c4 = (long long)Bq * Hh * Tt / 4;
        if (gid < c4) ((int4*)g_cnt)[gid] = make_int4(0, 0, 0, 0);
    }

    int token0 = blockIdx.x * 8;
    int bh = token0 / Tt;
    int h = bh % Hh;
    const float* mh = means + (size_t)h * NCc * Dd;
    for (int i = threadIdx.x; i < NCc * Dd; i += blockDim.x) sm[i] = mh[i];
    if (threadIdx.x == 0) saux = 0.f;
    __syncthreads();

    int warp = threadIdx.x >> 5, lane = threadIdx.x & 31;
    int token = token0 + warp;
    int t = token & (Tt - 1);

    float2 kv = ((const float2*)(k + (size_t)token * Dd))[lane];
    float ss = kv.x * kv.x + kv.y * kv.y;
#pragma unroll
    for (int o = 16; o; o >>= 1) ss += __shfl_xor_sync(0xffffffffu, ss, o);
    float inv = rsqrtf(ss);
    float2 xv = make_float2(kv.x * inv, kv.y * inv);

    float dl[NCc];
#pragma unroll
    for (int c = 0; c < NCc; c++)
        dl[c] = xv.x * sm[c * Dd + 2 * lane] + xv.y * sm[c * Dd + 2 * lane + 1];
#pragma unroll
    for (int o = 16; o; o >>= 1) {
#pragma unroll
        for (int c = 0; c < NCc; c++)
            dl[c] += __shfl_xor_sync(0xffffffffu, dl[c], o);
    }
    int bestc = 0;
    float bestv = dl[0];
#pragma unroll
    for (int c = 1; c < NCc; c++)
        if (dl[c] > bestv) { bestv = dl[c]; bestc = c; }

    if (lane == 0) {
#pragma unroll
        for (int c = 0; c < NCc; c++) sdl[c][warp] = dl[c];
    }

    float mx = sm[bestc * Dd + 2 * lane];
    float my = sm[bestc * Dd + 2 * lane + 1];
    float ex = xv.x - mx, ey = xv.y - my;
    float e = ex * ex + ey * ey;
#pragma unroll
    for (int o = 16; o; o >>= 1) e += __shfl_xor_sync(0xffffffffu, e, o);
    if (lane == 0) atomicAdd(&saux, e);
    __syncthreads();

    if (threadIdx.x < 128) {
        int c = threadIdx.x >> 3, tt = threadIdx.x & 7;
        int tbase = token0 & (Tt - 1);
        g_dists[((size_t)bh * NCc + c) * Tt + tbase + tt] = sdl[c][tt];
    }
    if (threadIdx.x == 0) g_aux_part[blockIdx.x] = saux;
}

// ---------------- kernel 2: radix-select top-WSZ per (b,h,c) (+ zero out) ----
__device__ __forceinline__ unsigned warp_incl_scan(unsigned v, int lane) {
#pragma unroll
    for (int off = 1; off < 32; off <<= 1) {
        unsigned t = __shfl_up_sync(0xffffffffu, v, off);
        if (lane >= off) v += t;
    }
    return v;
}

__device__ __forceinline__ void find_bin(unsigned* h, unsigned* wsum,
                                         unsigned* s_bin, unsigned* s_k, int tid) {
    int lane = tid & 31, w = tid >> 5;
    unsigned K = *s_k;
    unsigned tot = 0;
#pragma unroll
    for (int r = 0; r < 16; r++) tot += h[tid * 16 + r];
    unsigned p = warp_incl_scan(tot, lane);
    if (lane == 31) wsum[w] = p;
    __syncthreads();
    unsigned off = 0, S = 0;
#pragma unroll
    for (int i = 0; i < 8; i++) {
        unsigned x = wsum[i];
        S += x;
        if (i < w) off += x;
    }
    unsigned above = S - (p + off);
    unsigned run = above;
#pragma unroll
    for (int r = 15; r >= 0; r--) {
        unsigned cc = h[tid * 16 + r];
        run += cc;
        if (run >= K && run - cc < K) {
            *s_bin = (unsigned)(tid * 16 + r);
            *s_k = K - (run - cc);
        }
    }
    __syncthreads();
}

__global__ void __launch_bounds__(256) topk_kernel(float* __restrict__ out) {
    __shared__ unsigned su[Tt];
    __shared__ unsigned h[4096];
    __shared__ unsigned wsum[8];
    __shared__ unsigned s_bin, s_k;
    int tid = threadIdx.x;
    int lane = tid & 31, w = tid >> 5;
    int bhc = blockIdx.x;
    const float* dc = g_dists + (size_t)bhc * Tt;

    {
        float4* o4 = (float4*)out + (size_t)blockIdx.x * 4096;
        for (int i = tid; i < 4096; i += 256)
            o4[i] = make_float4(0.f, 0.f, 0.f, 0.f);
    }

    for (int i = tid; i < Tt; i += 256) {
        unsigned uu = __float_as_uint(dc[i]);
        uu = (uu & 0x80000000u) ? ~uu : (uu | 0x80000000u);
        su[i] = uu;
        h[i] = 0u;
    }
    if (tid == 0) s_k = WSZc;
    __syncthreads();

    for (int i = tid; i < Tt; i += 256) atomicAdd(&h[su[i] >> 20], 1u);
    __syncthreads();
    find_bin(h, wsum, &s_bin, &s_k, tid);
    unsigned b1 = s_bin;
    for (int i = tid; i < 4096; i += 256) h[i] = 0u;
    __syncthreads();

    for (int i = tid; i < Tt; i += 256)
        if ((su[i] >> 20) == b1) atomicAdd(&h[(su[i] >> 8) & 0xFFFu], 1u);
    __syncthreads();
    find_bin(h, wsum, &s_bin, &s_k, tid);
    unsigned b2 = s_bin;
    for (int i = tid; i < 4096; i += 256) h[i] = 0u;
    __syncthreads();

    unsigned hi20 = (b1 << 12) | b2;
    for (int i = tid; i < Tt; i += 256)
        if ((su[i] >> 8) == hi20) atomicAdd(&h[su[i] & 0xFFu], 1u);
    __syncthreads();
    find_bin(h, wsum, &s_bin, &s_k, tid);
    unsigned b3 = s_bin;
    unsigned m = s_k;
    unsigned thr = (b1 << 20) | (b2 << 8) | b3;

    unsigned gt = 0, eq = 0;
    int base = tid * 16;
#pragma unroll
    for (int r = 0; r < 16; r++) {
        unsigned uu = su[base + r];
        gt += (uu > thr);
        eq += (uu == thr);
    }
    unsigned mypack = (gt << 16) | eq;
    unsigned p = warp_incl_scan(mypack, lane);
    if (lane == 31) wsum[w] = p;
    __syncthreads();
    unsigned off = 0;
#pragma unroll
    for (int i = 0; i < 8; i++)
        if (i < w) off += wsum[i];
    unsigned excl = p + off - mypack;
    unsigned gtb = excl >> 16, eqb = excl & 0xFFFFu;
    int bh = bhc >> 4;
#pragma unroll
    for (int r = 0; r < 16; r++) {
        unsigned uu = su[base + r];
        if (uu > thr) {
            unsigned emin = eqb < m ? eqb : m;
            int pos = (int)(gtb + emin);
            g_idx[(size_t)bhc * WSZc + pos] = base + r;
            atomicAdd(&g_cnt[bh * Tt + base + r], 1);
            gtb++;
        } else if (uu == thr) {
            if (eqb < m) {
                int pos = (int)(gtb + eqb);
                g_idx[(size_t)bhc * WSZc + pos] = base + r;
                atomicAdd(&g_cnt[bh * Tt + base + r], 1);
            }
            eqb++;
        }
    }
}

// ---------------- kernel 3: fp16 m16n8k16 tensor-core windowed attention -----
// 512 threads = 16 warps. SMSP-balanced tile permutation: warp w computes
// row-tile t = perm(w) so each SMSP's causal workload sums to exactly 68 units.
__device__ __forceinline__ unsigned pack2h(float lo, float hi) {
    unsigned u;
    asm("cvt.rn.f16x2.f32 %0, %1, %2;" : "=r"(u) : "f"(hi), "f"(lo));
    return u;
}
__device__ __forceinline__ unsigned short f2h(float f) {
    unsigned short h;
    asm("cvt.rn.f16.f32 %0, %1;" : "=h"(h) : "f"(f));
    return h;
}
__device__ __forceinline__ void mma16(float* d, const unsigned* a, uint2 b) {
    asm volatile("mma.sync.aligned.m16n8k16.row.col.f32.f16.f16.f32 "
                 "{%0,%1,%2,%3}, {%4,%5,%6,%7}, {%8,%9}, {%0,%1,%2,%3};"
                 : "+f"(d[0]), "+f"(d[1]), "+f"(d[2]), "+f"(d[3])
                 : "r"(a[0]), "r"(a[1]), "r"(a[2]), "r"(a[3]), "r"(b.x), "r"(b.y));
}

__device__ __forceinline__ void epi_vals(int t, int jc, int nt, int g, int c,
                                         float* s, float& l0, float& l1) {
    int i0 = 16 * t + g, i1 = i0 + 8;
    int j0 = 64 * jc + 8 * nt + 2 * c, j1 = j0 + 1;
    s[0] = (j0 > i0) ? 0.f : (j0 == i0) ? ((i0 == 0) ? 1.f : 0.f) : __expf(s[0] * 0.125f);
    s[1] = (j1 > i0) ? 0.f : (j1 == i0) ? 0.f : __expf(s[1] * 0.125f);
    s[2] = (j0 > i1) ? 0.f : (j0 == i1) ? 0.f : __expf(s[2] * 0.125f);
    s[3] = (j1 > i1) ? 0.f : (j1 == i1) ? 0.f : __expf(s[3] * 0.125f);
    l0 += s[0] + s[1];
    l1 += s[2] + s[3];
}

#define KV_BUF 2048                        // u32 per chunk per operand (fp16)
#define ATTN_SMEM_BYTES (8 * KV_BUF * 4)   // KF[4] + VF[4] = 64KB

__global__ void __launch_bounds__(512, 1) attn_kernel(const float* __restrict__ q,
                                                      const float* __restrict__ k,
                                                      const float* __restrict__ v,
                                                      float* __restrict__ out) {
    extern __shared__ unsigned smu[];  // [KF0..KF3, VF0..VF3]
    __shared__ int sidx[WSZc];

    int tid = threadIdx.x;
    int bhc = blockIdx.x;
    int bh = bhc >> 4;
    int w = tid >> 5, lane = tid & 31;
    int g = lane >> 2, c = lane & 3;

    // SMSP-balanced permutation: quads {0,1,2,3},{7,6,5,4},{8,9,10,11},{15,14,13,12}
    int t = 4 * (w >> 2) + (((w >> 2) & 1) ? (3 - (w & 3)) : (w & 3));

    if (tid < WSZc) sidx[tid] = g_idx[(size_t)bhc * WSZc + tid];
    __syncthreads();

    // ---- staging: threads 0-255 K (normalize in-thread), 256-511 V ----
    if (tid < 256) {
        int gj = sidx[tid];
        int jcc = tid >> 6, r = tid & 63;
        const float4* ks4 = (const float4*)(k + ((size_t)bh * Tt + gj) * Dd);
        unsigned* KF = smu + jcc * KV_BUF;
        int nt = r >> 3, gk = r & 7;
        float4 kv[16];
        float ss = 0.f;
#pragma unroll
        for (int e = 0; e < 16; e++) {
            kv[e] = ks4[e];
            ss += kv[e].x * kv[e].x + kv[e].y * kv[e].y +
                  kv[e].z * kv[e].z + kv[e].w * kv[e].w;
        }
        float inv = rsqrtf(ss);
        // KF B-frag: reg0 = {kn[16ks+2c], kn[16ks+2c+1]}, reg1 = d+8
#pragma unroll
        for (int ks = 0; ks < 4; ks++) {
#pragma unroll
            for (int cc = 0; cc < 4; cc++) {
                int e0 = 4 * ks + (cc >> 1);
                float lo0, hi0, lo1, hi1;
                if (cc & 1) {
                    lo0 = kv[e0].z; hi0 = kv[e0].w;
                    lo1 = kv[e0 + 2].z; hi1 = kv[e0 + 2].w;
                } else {
                    lo0 = kv[e0].x; hi0 = kv[e0].y;
                    lo1 = kv[e0 + 2].x; hi1 = kv[e0 + 2].y;
                }
                unsigned r0 = pack2h(lo0 * inv, hi0 * inv);
                unsigned r1 = pack2h(lo1 * inv, hi1 * inv);
                *(uint2*)&KF[((ks * 8 + nt) * 32 + gk * 4 + cc) * 2] = make_uint2(r0, r1);
            }
        }
    } else {
        int rr = tid - 256;
        int gj = sidx[rr];
        int jcc = rr >> 6, r = rr & 63;
        const float4* vs4 = (const float4*)(v + ((size_t)bh * Tt + gj) * Dd);
        unsigned short* VH = (unsigned short*)(smu + 4 * KV_BUF + jcc * KV_BUF);
        // key r within chunk: kg = r>>4, position-in-16: reg*8 + 2c + p
        int kg = r >> 4, rloc = r & 15;
        int reg = (rloc >> 3) & 1, cc = (rloc & 7) >> 1, p = rloc & 1;
#pragma unroll
        for (int e = 0; e < 16; e++) {
            float4 vv = vs4[e];
            float vals[4] = {vv.x, vv.y, vv.z, vv.w};
#pragma unroll
            for (int j = 0; j < 4; j++) {
                int d = e * 4 + j;
                int nt2 = d >> 3, gv = d & 7;
                int addr32 = ((kg * 8 + nt2) * 32 + gv * 4 + cc) * 2 + reg;
                VH[addr32 * 2 + p] = f2h(vals[j]);
            }
        }
    }

    // ---- Q A-fragments (fp16) into registers (warp w owns tile t) ----
    unsigned A[4][4];
    {
        const float* qb = q + (size_t)bh * Tt * Dd;
        const float* r0 = qb + (size_t)sidx[16 * t + g] * Dd;
        const float* r1 = qb + (size_t)sidx[16 * t + g + 8] * Dd;
#pragma unroll
        for (int ks = 0; ks < 4; ks++) {
            int d0 = 16 * ks + 2 * c;
            A[ks][0] = pack2h(r0[d0], r0[d0 + 1]);
            A[ks][1] = pack2h(r1[d0], r1[d0 + 1]);
            A[ks][2] = pack2h(r0[d0 + 8], r0[d0 + 9]);
            A[ks][3] = pack2h(r1[d0 + 8], r1[d0 + 9]);
        }
    }

    float O[8][4];
#pragma unroll
    for (int nt = 0; nt < 8; nt++)
#pragma unroll
        for (int r = 0; r < 4; r++) O[nt][r] = 0.f;
    float lp[2] = {0.f, 0.f};

    __syncthreads();   // the ONLY mainloop barrier

    for (int jc = 0; jc < 4; jc++) {
        int lim = 2 * t + 1 - 8 * jc;
        if (lim < 0) break;
        const unsigned* KF = smu + jc * KV_BUF;
        const unsigned* VF = smu + 4 * KV_BUF + jc * KV_BUF;

#pragma unroll
        for (int nt = 0; nt < 8; nt += 2) {
            if (nt > lim) break;
            bool two = (nt + 1 <= lim);
            float sa[4] = {0.f, 0.f, 0.f, 0.f};  // nt,   ks 0-1
            float sb[4] = {0.f, 0.f, 0.f, 0.f};  // nt,   ks 2-3
            float sc[4] = {0.f, 0.f, 0.f, 0.f};  // nt+1, ks 0-1
            float sd[4] = {0.f, 0.f, 0.f, 0.f};  // nt+1, ks 2-3
#pragma unroll
            for (int ks = 0; ks < 2; ks++) {
                uint2 b0 = *(const uint2*)&KF[((ks * 8 + nt) * 32 + lane) * 2];
                uint2 b1 = *(const uint2*)&KF[(((ks + 2) * 8 + nt) * 32 + lane) * 2];
                mma16(sa, A[ks], b0);
                mma16(sb, A[ks + 2], b1);
                if (two) {
                    uint2 b2 = *(const uint2*)&KF[((ks * 8 + nt + 1) * 32 + lane) * 2];
                    uint2 b3 = *(const uint2*)&KF[(((ks + 2) * 8 + nt + 1) * 32 + lane) * 2];
                    mma16(sc, A[ks], b2);
                    mma16(sd, A[ks + 2], b3);
                }
            }
#pragma unroll
            for (int r = 0; r < 4; r++) { sa[r] += sb[r]; sc[r] += sd[r]; }

            epi_vals(t, jc, nt, g, c, sa, lp[0], lp[1]);
            if (two) epi_vals(t, jc, nt + 1, g, c, sc, lp[0], lp[1]);
            // else sc stays all-zero -> contributes nothing

            // P 16x16 A-fragment = the two accumulators packed (no shuffles)
            unsigned P[4];
            P[0] = pack2h(sa[0], sa[1]);
            P[1] = pack2h(sa[2], sa[3]);
            P[2] = pack2h(sc[0], sc[1]);
            P[3] = pack2h(sc[2], sc[3]);

            int kg = nt >> 1;
#pragma unroll
            for (int nt2 = 0; nt2 < 8; nt2++) {
                uint2 bv = *(const uint2*)&VF[((kg * 8 + nt2) * 32 + lane) * 2];
                mma16(O[nt2], P, bv);
            }
        }
    }

    // ---- row-sum reduce across quad, normalize, scatter ----
    float rs[2];
#pragma unroll
    for (int hf = 0; hf < 2; hf++) {
        float s = lp[hf];
        s += __shfl_xor_sync(0xffffffffu, s, 1);
        s += __shfl_xor_sync(0xffffffffu, s, 2);
        rs[hf] = 1.f / s;
    }
    {
        float* ob = out + (size_t)bh * Tt * Dd;
        float* o0 = ob + (size_t)sidx[16 * t + g] * Dd;
        float* o1 = ob + (size_t)sidx[16 * t + g + 8] * Dd;
#pragma unroll
        for (int nt2 = 0; nt2 < 8; nt2++) {
            int col = 8 * nt2 + 2 * c;
            atomicAdd(o0 + col, O[nt2][0] * rs[0]);
            atomicAdd(o0 + col + 1, O[nt2][1] * rs[0]);
            atomicAdd(o1 + col, O[nt2][2] * rs[1]);
            atomicAdd(o1 + col + 1, O[nt2][3] * rs[1]);
        }
    }
}

// ---------------- kernel 4: divide by count + aux loss ----------------
__global__ void finalize_kernel(float* out, int out_size) {
    const int n = Bq * Hh * Tt * Dd;
    const int n4 = n / 4;
    int i = blockIdx.x * blockDim.x + threadIdx.x;
    int stride = gridDim.x * blockDim.x;
    for (int p = i; p < n4; p += stride) {
        float4 o = ((float4*)out)[p];
        float cc = (float)g_cnt[p >> 4];
        float inv = 1.f / (cc + 1e-5f);
        o.x *= inv; o.y *= inv; o.z *= inv; o.w *= inv;
        ((float4*)out)[p] = o;
    }
    if (blockIdx.x == 0) {
        __shared__ float sred[256];
        float s = 0.f;
        for (int p = threadIdx.x; p < Bq * Hh * Tt / 8; p += 256) s += g_aux_part[p];
        sred[threadIdx.x] = s;
        __syncthreads();
        for (int off = 128; off; off >>= 1) {
            if (threadIdx.x < off) sred[threadIdx.x] += sred[threadIdx.x + off];
            __syncthreads();
        }
        if (threadIdx.x == 0 && out_size > n)
            out[n] = sred[0] * (1e-4f / (float)n);
    }
}

// ---------------- launch ----------------
extern "C" void kernel_launch(void* const* d_in, const int* in_sizes, int n_in,
                              void* d_out, int out_size) {
    const float* q = (const float*)d_in[0];
    const float* k = (const float*)d_in[1];
    const float* v = (const float*)d_in[2];
    const float* means = (const float*)d_in[3];
    float* out = (float*)d_out;

    cudaFuncSetAttribute(attn_kernel, cudaFuncAttributeMaxDynamicSharedMemorySize,
                         ATTN_SMEM_BYTES);

    route_kernel<<<Bq * Hh * Tt / 8, 256>>>(k, means);
    topk_kernel<<<Bq * Hh * NCc, 256>>>(out);
    attn_kernel<<<Bq * Hh * NCc, 512, ATTN_SMEM_BYTES>>>(q, k, v, out);
    finalize_kernel<<<2048, 256>>>(out, out_size);
}